// round 6
// baseline (speedup 1.0000x reference)
#include <cuda_runtime.h>
#include <cuda_bf16.h>
#include <math.h>
#include <stdint.h>

#define BATCH 4
#define SEQ 1024
#define DMODEL 1024
#define NHEAD 16
#define DHEAD 64
#define DFF 4096
#define MROWS (BATCH * SEQ)

__device__ float g_h[MROWS * DMODEL];
__device__ float g_attn[MROWS * DMODEL];
__device__ float g_x1[MROWS * DMODEL];
__device__ float g_mid[MROWS * DFF];

__device__ __forceinline__ uint32_t f2tf32(float f) {
    uint32_t u;
    asm volatile("cvt.rna.tf32.f32 %0, %1;" : "=r"(u) : "f"(f));
    return u;
}

// ---------------------------------------------------------------------------
// LayerNorm
// ---------------------------------------------------------------------------
__global__ __launch_bounds__(256) void ln_kernel(
    const float* __restrict__ x, const float* __restrict__ gam,
    const float* __restrict__ bet, float* __restrict__ out)
{
    int row = blockIdx.x;
    const float* xr = x + (size_t)row * DMODEL;
    float v[4];
    float s = 0.f, s2 = 0.f;
#pragma unroll
    for (int i = 0; i < 4; i++) {
        v[i] = xr[threadIdx.x + i * 256];
        s += v[i];
        s2 += v[i] * v[i];
    }
#pragma unroll
    for (int o = 16; o; o >>= 1) {
        s  += __shfl_xor_sync(0xffffffffu, s, o);
        s2 += __shfl_xor_sync(0xffffffffu, s2, o);
    }
    __shared__ float red[2][8];
    int w = threadIdx.x >> 5, l = threadIdx.x & 31;
    if (l == 0) { red[0][w] = s; red[1][w] = s2; }
    __syncthreads();
    s = 0.f; s2 = 0.f;
#pragma unroll
    for (int i = 0; i < 8; i++) { s += red[0][i]; s2 += red[1][i]; }
    float mean = s * (1.0f / DMODEL);
    float var  = s2 * (1.0f / DMODEL) - mean * mean;
    float rstd = rsqrtf(var + 1e-5f);
    float* orow = out + (size_t)row * DMODEL;
#pragma unroll
    for (int i = 0; i < 4; i++) {
        int c = threadIdx.x + i * 256;
        orow[c] = (v[i] - mean) * rstd * gam[c] + bet[c];
    }
}

// ---------------------------------------------------------------------------
// TF32 tensor-core flash attention (identical to R3 best).
// ---------------------------------------------------------------------------
#define KST 68
#define VST 72
#define PST 68
#define ATTN_SMEM ((64 * KST + 64 * VST + 128 * PST) * 4)

__global__ __launch_bounds__(256) void attn_tc(
    const float* __restrict__ Qb, const float* __restrict__ Kb,
    const float* __restrict__ Vb, float* __restrict__ Ob)
{
    extern __shared__ float sm[];
    float* Ks = sm;
    float* Vs = sm + 64 * KST;
    float* Ps = sm + 64 * KST + 64 * VST;

    int bh = blockIdx.x;
    int b = bh >> 4, h = bh & 15;
    int q0 = blockIdx.y << 7;
    int t = threadIdx.x, w = t >> 5, lane = t & 31;
    int g = lane >> 2, tig = lane & 3;
    int qrow = w * 16 + g;

    size_t base = ((size_t)b * SEQ) * DMODEL + (size_t)h * DHEAD;
    const float* Qp = Qb + base;
    const float* Kp = Kb + base;
    const float* Vp = Vb + base;

    for (int i = t; i < 128 * 16; i += 256) {
        int r = i >> 4, c4 = (i & 15) * 4;
        float4 v = *(const float4*)&Qp[(size_t)(q0 + r) * DMODEL + c4];
        v.x *= 0.125f; v.y *= 0.125f; v.z *= 0.125f; v.w *= 0.125f;
        *(float4*)&Ps[r * PST + c4] = v;
    }
    __syncthreads();

    uint32_t qf[8][4];
#pragma unroll
    for (int ks = 0; ks < 8; ks++) {
        int kk = ks * 8;
        qf[ks][0] = f2tf32(Ps[qrow * PST + kk + tig]);
        qf[ks][1] = f2tf32(Ps[(qrow + 8) * PST + kk + tig]);
        qf[ks][2] = f2tf32(Ps[qrow * PST + kk + tig + 4]);
        qf[ks][3] = f2tf32(Ps[(qrow + 8) * PST + kk + tig + 4]);
    }

    float oacc[8][4];
#pragma unroll
    for (int i = 0; i < 8; i++)
#pragma unroll
        for (int v = 0; v < 4; v++) oacc[i][v] = 0.f;
    float m_lo = -3.4e38f, m_hi = -3.4e38f, l_lo = 0.f, l_hi = 0.f;
    __syncthreads();

    for (int kt = 0; kt < SEQ / 64; kt++) {
        int k0 = kt << 6;
        for (int i = t; i < 64 * 16; i += 256) {
            int r = i >> 4, c4 = (i & 15) * 4;
            *(float4*)&Ks[r * KST + c4] =
                *(const float4*)&Kp[(size_t)(k0 + r) * DMODEL + c4];
            *(float4*)&Vs[r * VST + c4] =
                *(const float4*)&Vp[(size_t)(k0 + r) * DMODEL + c4];
        }
        __syncthreads();

        float sacc[8][4];
#pragma unroll
        for (int i = 0; i < 8; i++)
#pragma unroll
            for (int v = 0; v < 4; v++) sacc[i][v] = 0.f;
#pragma unroll
        for (int ks = 0; ks < 8; ks++) {
            int kk = ks * 8;
#pragma unroll
            for (int ni = 0; ni < 8; ni++) {
                uint32_t b0 = f2tf32(Ks[(ni * 8 + g) * KST + kk + tig]);
                uint32_t b1 = f2tf32(Ks[(ni * 8 + g) * KST + kk + tig + 4]);
                asm volatile(
                    "mma.sync.aligned.m16n8k8.row.col.f32.tf32.tf32.f32 "
                    "{%0,%1,%2,%3}, {%4,%5,%6,%7}, {%8,%9}, {%0,%1,%2,%3};\n"
                    : "+f"(sacc[ni][0]), "+f"(sacc[ni][1]),
                      "+f"(sacc[ni][2]), "+f"(sacc[ni][3])
                    : "r"(qf[ks][0]), "r"(qf[ks][1]), "r"(qf[ks][2]), "r"(qf[ks][3]),
                      "r"(b0), "r"(b1));
            }
        }

        float tl = -3.4e38f, th = -3.4e38f;
#pragma unroll
        for (int ni = 0; ni < 8; ni++) {
            tl = fmaxf(tl, fmaxf(sacc[ni][0], sacc[ni][1]));
            th = fmaxf(th, fmaxf(sacc[ni][2], sacc[ni][3]));
        }
        tl = fmaxf(tl, __shfl_xor_sync(0xffffffffu, tl, 1));
        tl = fmaxf(tl, __shfl_xor_sync(0xffffffffu, tl, 2));
        th = fmaxf(th, __shfl_xor_sync(0xffffffffu, th, 1));
        th = fmaxf(th, __shfl_xor_sync(0xffffffffu, th, 2));
        float nm_lo = fmaxf(m_lo, tl), nm_hi = fmaxf(m_hi, th);
        float corr_lo = __expf(m_lo - nm_lo), corr_hi = __expf(m_hi - nm_hi);
        m_lo = nm_lo; m_hi = nm_hi;

        float sum_lo = 0.f, sum_hi = 0.f;
#pragma unroll
        for (int ni = 0; ni < 8; ni++) {
            float e0 = __expf(sacc[ni][0] - nm_lo);
            float e1 = __expf(sacc[ni][1] - nm_lo);
            float e2 = __expf(sacc[ni][2] - nm_hi);
            float e3 = __expf(sacc[ni][3] - nm_hi);
            sum_lo += e0 + e1; sum_hi += e2 + e3;
            int c = ni * 8 + 2 * tig;
            Ps[qrow * PST + c]           = __uint_as_float(f2tf32(e0));
            Ps[qrow * PST + c + 1]       = __uint_as_float(f2tf32(e1));
            Ps[(qrow + 8) * PST + c]     = __uint_as_float(f2tf32(e2));
            Ps[(qrow + 8) * PST + c + 1] = __uint_as_float(f2tf32(e3));
        }
        sum_lo += __shfl_xor_sync(0xffffffffu, sum_lo, 1);
        sum_lo += __shfl_xor_sync(0xffffffffu, sum_lo, 2);
        sum_hi += __shfl_xor_sync(0xffffffffu, sum_hi, 1);
        sum_hi += __shfl_xor_sync(0xffffffffu, sum_hi, 2);
        l_lo = l_lo * corr_lo + sum_lo;
        l_hi = l_hi * corr_hi + sum_hi;

#pragma unroll
        for (int ni = 0; ni < 8; ni++) {
            oacc[ni][0] *= corr_lo; oacc[ni][1] *= corr_lo;
            oacc[ni][2] *= corr_hi; oacc[ni][3] *= corr_hi;
        }
        __syncwarp();

#pragma unroll
        for (int ks = 0; ks < 8; ks++) {
            int kk = ks * 8;
            uint32_t pa0 = __float_as_uint(Ps[qrow * PST + kk + tig]);
            uint32_t pa1 = __float_as_uint(Ps[(qrow + 8) * PST + kk + tig]);
            uint32_t pa2 = __float_as_uint(Ps[qrow * PST + kk + tig + 4]);
            uint32_t pa3 = __float_as_uint(Ps[(qrow + 8) * PST + kk + tig + 4]);
#pragma unroll
            for (int ni = 0; ni < 8; ni++) {
                uint32_t b0 = f2tf32(Vs[(kk + tig) * VST + ni * 8 + g]);
                uint32_t b1 = f2tf32(Vs[(kk + tig + 4) * VST + ni * 8 + g]);
                asm volatile(
                    "mma.sync.aligned.m16n8k8.row.col.f32.tf32.tf32.f32 "
                    "{%0,%1,%2,%3}, {%4,%5,%6,%7}, {%8,%9}, {%0,%1,%2,%3};\n"
                    : "+f"(oacc[ni][0]), "+f"(oacc[ni][1]),
                      "+f"(oacc[ni][2]), "+f"(oacc[ni][3])
                    : "r"(pa0), "r"(pa1), "r"(pa2), "r"(pa3),
                      "r"(b0), "r"(b1));
            }
        }
        __syncthreads();
    }

    float inv_lo = 1.f / l_lo, inv_hi = 1.f / l_hi;
    float* Op = Ob + base;
#pragma unroll
    for (int ni = 0; ni < 8; ni++) {
        int c = ni * 8 + 2 * tig;
        *(float2*)&Op[(size_t)(q0 + qrow) * DMODEL + c] =
            make_float2(oacc[ni][0] * inv_lo, oacc[ni][1] * inv_lo);
        *(float2*)&Op[(size_t)(q0 + qrow + 8) * DMODEL + c] =
            make_float2(oacc[ni][2] * inv_hi, oacc[ni][3] * inv_hi);
    }
}

// ---------------------------------------------------------------------------
// TF32 GEMM v2: 128x128x32 tiles, 3-stage cp.async ring, 1 barrier/iter.
// 256 threads = 8 warps (2m x 4n), warp tile 64x32, 64 HMMA/thread/iter.
// Smem/stage: A[128][36] (bank 4m+k all-distinct), B[32][136] (8k+n distinct).
// ---------------------------------------------------------------------------
#define AST2 36
#define BST2 136
#define STAGE_F (128 * AST2 + 32 * BST2)       // 8960 floats
#define GEMM_SMEM (3 * STAGE_F * 4)            // 107520 bytes

template <bool RELU, bool RES>
__global__ __launch_bounds__(256, 2) void gemm_tc(
    const float* __restrict__ A, const float* __restrict__ Bm,
    const float* __restrict__ bias, const float* __restrict__ resid,
    float* __restrict__ C, int M, int N, int K)
{
    extern __shared__ float smem[];

    int tid = threadIdx.x;
    int wid = tid >> 5;
    int lane = tid & 31;
    int g = lane >> 2;
    int tig = lane & 3;
    int m0 = blockIdx.y * 128, n0 = blockIdx.x * 128;
    int m0w = (wid & 1) * 64;
    int n0w = (wid >> 1) * 32;

    float acc[4][4][4];
#pragma unroll
    for (int i = 0; i < 4; i++)
#pragma unroll
        for (int j = 0; j < 4; j++)
#pragma unroll
            for (int v = 0; v < 4; v++) acc[i][j][v] = 0.f;

    // load coords: A tile 128x32 (1024 float4), B tile 32x128 (1024 float4)
    // thread handles float4 idx = tid + j*256, j=0..3
    uint32_t sm_base = (uint32_t)__cvta_generic_to_shared(smem);

#define LOAD_STAGE(K0, ST)                                                        \
    do {                                                                          \
        uint32_t sb = sm_base + (ST) * STAGE_F * 4;                               \
        _Pragma("unroll")                                                         \
        for (int j = 0; j < 4; j++) {                                             \
            int idx = tid + j * 256;                                              \
            int ar = idx >> 3, ac = (idx & 7) * 4;                                \
            asm volatile("cp.async.ca.shared.global [%0], [%1], 16;\n" ::         \
                "r"(sb + (uint32_t)(ar * AST2 + ac) * 4),                         \
                "l"(A + (size_t)(m0 + ar) * K + (K0) + ac));                      \
        }                                                                         \
        _Pragma("unroll")                                                         \
        for (int j = 0; j < 4; j++) {                                             \
            int idx = tid + j * 256;                                              \
            int br = idx >> 5, bc = (idx & 31) * 4;                               \
            asm volatile("cp.async.ca.shared.global [%0], [%1], 16;\n" ::         \
                "r"(sb + (uint32_t)(128 * AST2 + br * BST2 + bc) * 4),            \
                "l"(Bm + (size_t)((K0) + br) * N + n0 + bc));                     \
        }                                                                         \
    } while (0)

    int KT = K >> 5;   // K/32
    LOAD_STAGE(0, 0);
    asm volatile("cp.async.commit_group;\n");
    LOAD_STAGE(32, 1);
    asm volatile("cp.async.commit_group;\n");

    for (int kt = 0; kt < KT; kt++) {
        asm volatile("cp.async.wait_group 1;\n");
        __syncthreads();
        int st = kt % 3;
        if (kt + 2 < KT) LOAD_STAGE((kt + 2) << 5, (kt + 2) % 3);
        asm volatile("cp.async.commit_group;\n");

        const float* as = smem + st * STAGE_F;
        const float* bs = as + 128 * AST2;
#pragma unroll
        for (int ks = 0; ks < 4; ks++) {
            int kk = ks * 8;
            uint32_t af[4][4], bf[4][2];
#pragma unroll
            for (int mi = 0; mi < 4; mi++) {
                const float* ap = as + (m0w + mi * 16 + g) * AST2 + kk + tig;
                af[mi][0] = f2tf32(ap[0]);
                af[mi][1] = f2tf32(ap[8 * AST2]);
                af[mi][2] = f2tf32(ap[4]);
                af[mi][3] = f2tf32(ap[8 * AST2 + 4]);
            }
#pragma unroll
            for (int ni = 0; ni < 4; ni++) {
                const float* bp = bs + (kk + tig) * BST2 + n0w + ni * 8 + g;
                bf[ni][0] = f2tf32(bp[0]);
                bf[ni][1] = f2tf32(bp[4 * BST2]);
            }
#pragma unroll
            for (int mi = 0; mi < 4; mi++)
#pragma unroll
                for (int ni = 0; ni < 4; ni++) {
                    asm volatile(
                        "mma.sync.aligned.m16n8k8.row.col.f32.tf32.tf32.f32 "
                        "{%0,%1,%2,%3}, {%4,%5,%6,%7}, {%8,%9}, {%0,%1,%2,%3};\n"
                        : "+f"(acc[mi][ni][0]), "+f"(acc[mi][ni][1]),
                          "+f"(acc[mi][ni][2]), "+f"(acc[mi][ni][3])
                        : "r"(af[mi][0]), "r"(af[mi][1]), "r"(af[mi][2]), "r"(af[mi][3]),
                          "r"(bf[ni][0]), "r"(bf[ni][1]));
                }
        }
    }

#pragma unroll
    for (int mi = 0; mi < 4; mi++) {
        int r0 = m0 + m0w + mi * 16 + g;
#pragma unroll
        for (int ni = 0; ni < 4; ni++) {
            int c = n0 + n0w + ni * 8 + 2 * tig;
            float b0 = bias[c], b1 = bias[c + 1];
            float v0 = acc[mi][ni][0] + b0;
            float v1 = acc[mi][ni][1] + b1;
            float v2 = acc[mi][ni][2] + b0;
            float v3 = acc[mi][ni][3] + b1;
            if (RES) {
                v0 += resid[(size_t)r0 * N + c];
                v1 += resid[(size_t)r0 * N + c + 1];
                v2 += resid[(size_t)(r0 + 8) * N + c];
                v3 += resid[(size_t)(r0 + 8) * N + c + 1];
            }
            if (RELU) {
                v0 = fmaxf(v0, 0.f); v1 = fmaxf(v1, 0.f);
                v2 = fmaxf(v2, 0.f); v3 = fmaxf(v3, 0.f);
            }
            *(float2*)&C[(size_t)r0 * N + c] = make_float2(v0, v1);
            *(float2*)&C[(size_t)(r0 + 8) * N + c] = make_float2(v2, v3);
        }
    }
#undef LOAD_STAGE
}

// ---------------------------------------------------------------------------
extern "C" void kernel_launch(void* const* d_in, const int* in_sizes, int n_in,
                              void* d_out, int out_size)
{
    const float* tgt    = (const float*)d_in[0];
    const float* memory = (const float*)d_in[1];
    const float* sa_w   = (const float*)d_in[4];
    const float* sa_b   = (const float*)d_in[5];
    const float* mha_w  = (const float*)d_in[6];
    const float* mha_b  = (const float*)d_in[7];
    const float* ff_w1  = (const float*)d_in[8];
    const float* ff_b1  = (const float*)d_in[9];
    const float* ff_w2  = (const float*)d_in[10];
    const float* ff_b2  = (const float*)d_in[11];
    const float* ln1g   = (const float*)d_in[12];
    const float* ln1b   = (const float*)d_in[13];
    const float* ln2g   = (const float*)d_in[14];
    const float* ln2b   = (const float*)d_in[15];
    const float* ln3g   = (const float*)d_in[16];
    const float* ln3b   = (const float*)d_in[17];
    float* out = (float*)d_out;

    float *h, *attn, *x1, *mid;
    cudaGetSymbolAddress((void**)&h,    g_h);
    cudaGetSymbolAddress((void**)&attn, g_attn);
    cudaGetSymbolAddress((void**)&x1,   g_x1);
    cudaGetSymbolAddress((void**)&mid,  g_mid);

    cudaFuncSetAttribute(attn_tc, cudaFuncAttributeMaxDynamicSharedMemorySize, ATTN_SMEM);
    cudaFuncSetAttribute(gemm_tc<false, true>,
                         cudaFuncAttributeMaxDynamicSharedMemorySize, GEMM_SMEM);
    cudaFuncSetAttribute(gemm_tc<true, false>,
                         cudaFuncAttributeMaxDynamicSharedMemorySize, GEMM_SMEM);

    dim3 attn_grid(BATCH * NHEAD, SEQ / 128);
    dim3 gfc(DMODEL / 128, MROWS / 128);     // (8, 32)
    dim3 gff1(DFF / 128, MROWS / 128);       // (32, 32)

    // ---- self-attention block ----
    ln_kernel<<<MROWS, 256>>>(tgt, ln1g, ln1b, h);
    attn_tc<<<attn_grid, 256, ATTN_SMEM>>>(h, h, h, attn);
    gemm_tc<false, true><<<gfc, 256, GEMM_SMEM>>>(attn, sa_w, sa_b, tgt, x1,
                                                  MROWS, DMODEL, DMODEL);
    // ---- cross-attention block (Q=K=memory, V=LN2(x)) ----
    ln_kernel<<<MROWS, 256>>>(x1, ln2g, ln2b, h);
    attn_tc<<<attn_grid, 256, ATTN_SMEM>>>(memory, memory, h, attn);
    gemm_tc<false, true><<<gfc, 256, GEMM_SMEM>>>(attn, mha_w, mha_b, x1, out,
                                                  MROWS, DMODEL, DMODEL);
    // ---- FFN block ----
    ln_kernel<<<MROWS, 256>>>(out, ln3g, ln3b, h);
    gemm_tc<true, false><<<gff1, 256, GEMM_SMEM>>>(h, ff_w1, ff_b1, nullptr, mid,
                                                   MROWS, DFF, DMODEL);
    gemm_tc<false, true><<<gfc, 256, GEMM_SMEM>>>(mid, ff_w2, ff_b2, out, out,
                                                  MROWS, DMODEL, DFF);
}

// round 8
// speedup vs baseline: 1.3640x; 1.3640x over previous
#include <cuda_runtime.h>
#include <cuda_fp16.h>
#include <cuda_bf16.h>
#include <math.h>
#include <stdint.h>

#define BATCH 4
#define SEQ 1024
#define DMODEL 1024
#define NHEAD 16
#define DHEAD 64
#define DFF 4096
#define MROWS (BATCH * SEQ)

__device__ float g_h[MROWS * DMODEL];          // LN out (fp32)
__device__ float g_attn[MROWS * DMODEL];       // attention out
__device__ float g_x1[MROWS * DMODEL];         // residual stream
__device__ __half g_h16[MROWS * DMODEL];       // LN3 out (fp16)
__device__ __half g_mid16[MROWS * DFF];        // FFN hidden (fp16)
__device__ __half g_w1t[DFF * DMODEL];         // ff_w1^T fp16 [N][K]
__device__ __half g_w2t[DMODEL * DFF];         // ff_w2^T fp16 [N][K]

__device__ __forceinline__ uint32_t f2tf32(float f) {
    uint32_t u;
    asm volatile("cvt.rna.tf32.f32 %0, %1;" : "=r"(u) : "f"(f));
    return u;
}

// ---------------------------------------------------------------------------
// LayerNorm (F16OUT=1 writes __half)
// ---------------------------------------------------------------------------
template <int F16OUT>
__global__ __launch_bounds__(256) void ln_kernel(
    const float* __restrict__ x, const float* __restrict__ gam,
    const float* __restrict__ bet, float* __restrict__ out,
    __half* __restrict__ out16)
{
    int row = blockIdx.x;
    const float* xr = x + (size_t)row * DMODEL;
    float v[4];
    float s = 0.f, s2 = 0.f;
#pragma unroll
    for (int i = 0; i < 4; i++) {
        v[i] = xr[threadIdx.x + i * 256];
        s += v[i];
        s2 += v[i] * v[i];
    }
#pragma unroll
    for (int o = 16; o; o >>= 1) {
        s  += __shfl_xor_sync(0xffffffffu, s, o);
        s2 += __shfl_xor_sync(0xffffffffu, s2, o);
    }
    __shared__ float red[2][8];
    int w = threadIdx.x >> 5, l = threadIdx.x & 31;
    if (l == 0) { red[0][w] = s; red[1][w] = s2; }
    __syncthreads();
    s = 0.f; s2 = 0.f;
#pragma unroll
    for (int i = 0; i < 8; i++) { s += red[0][i]; s2 += red[1][i]; }
    float mean = s * (1.0f / DMODEL);
    float var  = s2 * (1.0f / DMODEL) - mean * mean;
    float rstd = rsqrtf(var + 1e-5f);
#pragma unroll
    for (int i = 0; i < 4; i++) {
        int c = threadIdx.x + i * 256;
        float y = (v[i] - mean) * rstd * gam[c] + bet[c];
        if (F16OUT) out16[(size_t)row * DMODEL + c] = __float2half_rn(y);
        else        out[(size_t)row * DMODEL + c] = y;
    }
}

// ---------------------------------------------------------------------------
// Weight transpose+convert: W[K,N] fp32 -> Wt[N,K] fp16
// ---------------------------------------------------------------------------
__global__ __launch_bounds__(256) void wcvt_kernel(
    const float* __restrict__ W, __half* __restrict__ Wt, int K, int N)
{
    __shared__ float tile[32][33];
    int k0 = blockIdx.y * 32, n0 = blockIdx.x * 32;
    int tx = threadIdx.x & 31, ty = threadIdx.x >> 5;
#pragma unroll
    for (int j = 0; j < 4; j++)
        tile[ty + 8 * j][tx] = W[(size_t)(k0 + ty + 8 * j) * N + n0 + tx];
    __syncthreads();
#pragma unroll
    for (int j = 0; j < 4; j++) {
        int n = n0 + ty + 8 * j, k = k0 + tx;
        Wt[(size_t)n * K + k] = __float2half_rn(tile[tx][ty + 8 * j]);
    }
}

// ---------------------------------------------------------------------------
// TF32 flash attention (unchanged R3-best)
// ---------------------------------------------------------------------------
#define KST 68
#define VST 72
#define PST 68
#define ATTN_SMEM ((64 * KST + 64 * VST + 128 * PST) * 4)

__global__ __launch_bounds__(256) void attn_tc(
    const float* __restrict__ Qb, const float* __restrict__ Kb,
    const float* __restrict__ Vb, float* __restrict__ Ob)
{
    extern __shared__ float sm[];
    float* Ks = sm;
    float* Vs = sm + 64 * KST;
    float* Ps = sm + 64 * KST + 64 * VST;

    int bh = blockIdx.x;
    int b = bh >> 4, h = bh & 15;
    int q0 = blockIdx.y << 7;
    int t = threadIdx.x, w = t >> 5, lane = t & 31;
    int g = lane >> 2, tig = lane & 3;
    int qrow = w * 16 + g;

    size_t base = ((size_t)b * SEQ) * DMODEL + (size_t)h * DHEAD;
    const float* Qp = Qb + base;
    const float* Kp = Kb + base;
    const float* Vp = Vb + base;

    for (int i = t; i < 128 * 16; i += 256) {
        int r = i >> 4, c4 = (i & 15) * 4;
        float4 v = *(const float4*)&Qp[(size_t)(q0 + r) * DMODEL + c4];
        v.x *= 0.125f; v.y *= 0.125f; v.z *= 0.125f; v.w *= 0.125f;
        *(float4*)&Ps[r * PST + c4] = v;
    }
    __syncthreads();

    uint32_t qf[8][4];
#pragma unroll
    for (int ks = 0; ks < 8; ks++) {
        int kk = ks * 8;
        qf[ks][0] = f2tf32(Ps[qrow * PST + kk + tig]);
        qf[ks][1] = f2tf32(Ps[(qrow + 8) * PST + kk + tig]);
        qf[ks][2] = f2tf32(Ps[qrow * PST + kk + tig + 4]);
        qf[ks][3] = f2tf32(Ps[(qrow + 8) * PST + kk + tig + 4]);
    }

    float oacc[8][4];
#pragma unroll
    for (int i = 0; i < 8; i++)
#pragma unroll
        for (int v = 0; v < 4; v++) oacc[i][v] = 0.f;
    float m_lo = -3.4e38f, m_hi = -3.4e38f, l_lo = 0.f, l_hi = 0.f;
    __syncthreads();

    for (int kt = 0; kt < SEQ / 64; kt++) {
        int k0 = kt << 6;
        for (int i = t; i < 64 * 16; i += 256) {
            int r = i >> 4, c4 = (i & 15) * 4;
            *(float4*)&Ks[r * KST + c4] =
                *(const float4*)&Kp[(size_t)(k0 + r) * DMODEL + c4];
            *(float4*)&Vs[r * VST + c4] =
                *(const float4*)&Vp[(size_t)(k0 + r) * DMODEL + c4];
        }
        __syncthreads();

        float sacc[8][4];
#pragma unroll
        for (int i = 0; i < 8; i++)
#pragma unroll
            for (int v = 0; v < 4; v++) sacc[i][v] = 0.f;
#pragma unroll
        for (int ks = 0; ks < 8; ks++) {
            int kk = ks * 8;
#pragma unroll
            for (int ni = 0; ni < 8; ni++) {
                uint32_t b0 = f2tf32(Ks[(ni * 8 + g) * KST + kk + tig]);
                uint32_t b1 = f2tf32(Ks[(ni * 8 + g) * KST + kk + tig + 4]);
                asm volatile(
                    "mma.sync.aligned.m16n8k8.row.col.f32.tf32.tf32.f32 "
                    "{%0,%1,%2,%3}, {%4,%5,%6,%7}, {%8,%9}, {%0,%1,%2,%3};\n"
                    : "+f"(sacc[ni][0]), "+f"(sacc[ni][1]),
                      "+f"(sacc[ni][2]), "+f"(sacc[ni][3])
                    : "r"(qf[ks][0]), "r"(qf[ks][1]), "r"(qf[ks][2]), "r"(qf[ks][3]),
                      "r"(b0), "r"(b1));
            }
        }

        float tl = -3.4e38f, th = -3.4e38f;
#pragma unroll
        for (int ni = 0; ni < 8; ni++) {
            tl = fmaxf(tl, fmaxf(sacc[ni][0], sacc[ni][1]));
            th = fmaxf(th, fmaxf(sacc[ni][2], sacc[ni][3]));
        }
        tl = fmaxf(tl, __shfl_xor_sync(0xffffffffu, tl, 1));
        tl = fmaxf(tl, __shfl_xor_sync(0xffffffffu, tl, 2));
        th = fmaxf(th, __shfl_xor_sync(0xffffffffu, th, 1));
        th = fmaxf(th, __shfl_xor_sync(0xffffffffu, th, 2));
        float nm_lo = fmaxf(m_lo, tl), nm_hi = fmaxf(m_hi, th);
        float corr_lo = __expf(m_lo - nm_lo), corr_hi = __expf(m_hi - nm_hi);
        m_lo = nm_lo; m_hi = nm_hi;

        float sum_lo = 0.f, sum_hi = 0.f;
#pragma unroll
        for (int ni = 0; ni < 8; ni++) {
            float e0 = __expf(sacc[ni][0] - nm_lo);
            float e1 = __expf(sacc[ni][1] - nm_lo);
            float e2 = __expf(sacc[ni][2] - nm_hi);
            float e3 = __expf(sacc[ni][3] - nm_hi);
            sum_lo += e0 + e1; sum_hi += e2 + e3;
            int c = ni * 8 + 2 * tig;
            Ps[qrow * PST + c]           = __uint_as_float(f2tf32(e0));
            Ps[qrow * PST + c + 1]       = __uint_as_float(f2tf32(e1));
            Ps[(qrow + 8) * PST + c]     = __uint_as_float(f2tf32(e2));
            Ps[(qrow + 8) * PST + c + 1] = __uint_as_float(f2tf32(e3));
        }
        sum_lo += __shfl_xor_sync(0xffffffffu, sum_lo, 1);
        sum_lo += __shfl_xor_sync(0xffffffffu, sum_lo, 2);
        sum_hi += __shfl_xor_sync(0xffffffffu, sum_hi, 1);
        sum_hi += __shfl_xor_sync(0xffffffffu, sum_hi, 2);
        l_lo = l_lo * corr_lo + sum_lo;
        l_hi = l_hi * corr_hi + sum_hi;

#pragma unroll
        for (int ni = 0; ni < 8; ni++) {
            oacc[ni][0] *= corr_lo; oacc[ni][1] *= corr_lo;
            oacc[ni][2] *= corr_hi; oacc[ni][3] *= corr_hi;
        }
        __syncwarp();

#pragma unroll
        for (int ks = 0; ks < 8; ks++) {
            int kk = ks * 8;
            uint32_t pa0 = __float_as_uint(Ps[qrow * PST + kk + tig]);
            uint32_t pa1 = __float_as_uint(Ps[(qrow + 8) * PST + kk + tig]);
            uint32_t pa2 = __float_as_uint(Ps[qrow * PST + kk + tig + 4]);
            uint32_t pa3 = __float_as_uint(Ps[(qrow + 8) * PST + kk + tig + 4]);
#pragma unroll
            for (int ni = 0; ni < 8; ni++) {
                uint32_t b0 = f2tf32(Vs[(kk + tig) * VST + ni * 8 + g]);
                uint32_t b1 = f2tf32(Vs[(kk + tig + 4) * VST + ni * 8 + g]);
                asm volatile(
                    "mma.sync.aligned.m16n8k8.row.col.f32.tf32.tf32.f32 "
                    "{%0,%1,%2,%3}, {%4,%5,%6,%7}, {%8,%9}, {%0,%1,%2,%3};\n"
                    : "+f"(oacc[ni][0]), "+f"(oacc[ni][1]),
                      "+f"(oacc[ni][2]), "+f"(oacc[ni][3])
                    : "r"(pa0), "r"(pa1), "r"(pa2), "r"(pa3),
                      "r"(b0), "r"(b1));
            }
        }
        __syncthreads();
    }

    float inv_lo = 1.f / l_lo, inv_hi = 1.f / l_hi;
    float* Op = Ob + base;
#pragma unroll
    for (int ni = 0; ni < 8; ni++) {
        int c = ni * 8 + 2 * tig;
        *(float2*)&Op[(size_t)(q0 + qrow) * DMODEL + c] =
            make_float2(oacc[ni][0] * inv_lo, oacc[ni][1] * inv_lo);
        *(float2*)&Op[(size_t)(q0 + qrow + 8) * DMODEL + c] =
            make_float2(oacc[ni][2] * inv_hi, oacc[ni][3] * inv_hi);
    }
}

// ---------------------------------------------------------------------------
// TF32 GEMM (exact R3 version) for the two fc projections
// ---------------------------------------------------------------------------
#define ASTRIDE 20
#define BSTRIDE 136

template <bool RELU, bool RES>
__global__ __launch_bounds__(256) void gemm_tc(
    const float* __restrict__ A, const float* __restrict__ Bm,
    const float* __restrict__ bias, const float* __restrict__ resid,
    float* __restrict__ C, int M, int N, int K)
{
    __shared__ float As[2][128 * ASTRIDE];
    __shared__ float Bs[2][16 * BSTRIDE];

    int tid = threadIdx.x;
    int wid = tid >> 5;
    int lane = tid & 31;
    int g = lane >> 2;
    int tig = lane & 3;
    int m0 = blockIdx.y * 128, n0 = blockIdx.x * 128;
    int m0w = (wid & 1) * 64;
    int n0w = (wid >> 1) * 32;

    int arow = tid >> 2, ac4 = (tid & 3) * 4;
    int brow = tid >> 5, bc4 = (tid & 31) * 4;
    const float* Ag = A + (size_t)(m0 + arow) * K + ac4;
    const float* Bg = Bm + (size_t)brow * N + n0 + bc4;

    uint32_t sA0 = (uint32_t)__cvta_generic_to_shared(&As[0][arow * ASTRIDE + ac4]);
    uint32_t sA1 = (uint32_t)__cvta_generic_to_shared(&As[1][arow * ASTRIDE + ac4]);
    uint32_t sB0 = (uint32_t)__cvta_generic_to_shared(&Bs[0][brow * BSTRIDE + bc4]);
    uint32_t sB1 = (uint32_t)__cvta_generic_to_shared(&Bs[1][brow * BSTRIDE + bc4]);
    const int A2G = 64, B2G = 8;

    float acc[4][4][4];
#pragma unroll
    for (int i = 0; i < 4; i++)
#pragma unroll
        for (int j = 0; j < 4; j++)
#pragma unroll
            for (int v = 0; v < 4; v++) acc[i][j][v] = 0.f;

#define LOAD_TILES(ST, K0)                                                        \
    do {                                                                          \
        uint32_t da = (ST) ? sA1 : sA0;                                           \
        uint32_t db = (ST) ? sB1 : sB0;                                           \
        asm volatile("cp.async.ca.shared.global [%0], [%1], 16;\n" ::             \
            "r"(da), "l"(Ag + (K0)));                                             \
        asm volatile("cp.async.ca.shared.global [%0], [%1], 16;\n" ::             \
            "r"(da + A2G * ASTRIDE * 4), "l"(Ag + (size_t)A2G * K + (K0)));       \
        asm volatile("cp.async.ca.shared.global [%0], [%1], 16;\n" ::             \
            "r"(db), "l"(Bg + (size_t)(K0) * N));                                 \
        asm volatile("cp.async.ca.shared.global [%0], [%1], 16;\n" ::             \
            "r"(db + B2G * BSTRIDE * 4), "l"(Bg + (size_t)((K0) + B2G) * N));     \
    } while (0)

    int KT = K >> 4;
    LOAD_TILES(0, 0);
    asm volatile("cp.async.commit_group;\n");

    for (int kt = 0; kt < KT; kt++) {
        if (kt + 1 < KT) {
            LOAD_TILES((kt + 1) & 1, (kt + 1) << 4);
            asm volatile("cp.async.commit_group;\n");
            asm volatile("cp.async.wait_group 1;\n");
        } else {
            asm volatile("cp.async.wait_group 0;\n");
        }
        __syncthreads();
        const float* as = As[kt & 1];
        const float* bs = Bs[kt & 1];
#pragma unroll
        for (int ks = 0; ks < 2; ks++) {
            int kk = ks * 8;
            uint32_t af[4][4], bf[4][2];
#pragma unroll
            for (int mi = 0; mi < 4; mi++) {
                const float* ap = as + (m0w + mi * 16 + g) * ASTRIDE + kk + tig;
                af[mi][0] = f2tf32(ap[0]);
                af[mi][1] = f2tf32(ap[8 * ASTRIDE]);
                af[mi][2] = f2tf32(ap[4]);
                af[mi][3] = f2tf32(ap[8 * ASTRIDE + 4]);
            }
#pragma unroll
            for (int ni = 0; ni < 4; ni++) {
                const float* bp = bs + (kk + tig) * BSTRIDE + n0w + ni * 8 + g;
                bf[ni][0] = f2tf32(bp[0]);
                bf[ni][1] = f2tf32(bp[4 * BSTRIDE]);
            }
#pragma unroll
            for (int mi = 0; mi < 4; mi++)
#pragma unroll
                for (int ni = 0; ni < 4; ni++) {
                    asm volatile(
                        "mma.sync.aligned.m16n8k8.row.col.f32.tf32.tf32.f32 "
                        "{%0,%1,%2,%3}, {%4,%5,%6,%7}, {%8,%9}, {%0,%1,%2,%3};\n"
                        : "+f"(acc[mi][ni][0]), "+f"(acc[mi][ni][1]),
                          "+f"(acc[mi][ni][2]), "+f"(acc[mi][ni][3])
                        : "r"(af[mi][0]), "r"(af[mi][1]), "r"(af[mi][2]), "r"(af[mi][3]),
                          "r"(bf[ni][0]), "r"(bf[ni][1]));
                }
        }
        __syncthreads();
    }

#pragma unroll
    for (int mi = 0; mi < 4; mi++) {
        int r0 = m0 + m0w + mi * 16 + g;
#pragma unroll
        for (int ni = 0; ni < 4; ni++) {
            int c = n0 + n0w + ni * 8 + 2 * tig;
            float b0 = bias[c], b1 = bias[c + 1];
            float v0 = acc[mi][ni][0] + b0;
            float v1 = acc[mi][ni][1] + b1;
            float v2 = acc[mi][ni][2] + b0;
            float v3 = acc[mi][ni][3] + b1;
            if (RES) {
                v0 += resid[(size_t)r0 * N + c];
                v1 += resid[(size_t)r0 * N + c + 1];
                v2 += resid[(size_t)(r0 + 8) * N + c];
                v3 += resid[(size_t)(r0 + 8) * N + c + 1];
            }
            if (RELU) {
                v0 = fmaxf(v0, 0.f); v1 = fmaxf(v1, 0.f);
                v2 = fmaxf(v2, 0.f); v3 = fmaxf(v3, 0.f);
            }
            *(float2*)&C[(size_t)r0 * N + c] = make_float2(v0, v1);
            *(float2*)&C[(size_t)(r0 + 8) * N + c] = make_float2(v2, v3);
        }
    }
#undef LOAD_TILES
}

// ---------------------------------------------------------------------------
// FP16 GEMM (FFN): A[M,K] fp16, Bt[N,K] fp16 (k-contig). 128x128x32 tiles,
// 2-stage double buffer, m16n8k16 fp32-acc, warp tile 64x32 (8 warps 2x4).
// Smem stride 56 halfs (bank map 28g+tig: conflict-free).
// EPI 0: fp16 out = relu(acc+bias).  EPI 1: fp32 out = acc+bias+resid.
// ---------------------------------------------------------------------------
#define HAST 56
#define HSTAGE_H (2 * 128 * HAST)              // halfs per stage (A then B)
#define HGEMM_SMEM (2 * HSTAGE_H * 2)          // bytes = 57344

template <int EPI>
__global__ __launch_bounds__(256) void hgemm(
    const __half* __restrict__ A, const __half* __restrict__ Bt,
    const float* __restrict__ bias, const float* __restrict__ resid,
    __half* __restrict__ C16, float* __restrict__ C32, int M, int N, int K)
{
    extern __shared__ __half hsm[];

    int tid = threadIdx.x;
    int wid = tid >> 5;
    int lane = tid & 31;
    int g = lane >> 2;
    int tig = lane & 3;
    int m0 = blockIdx.y * 128, n0 = blockIdx.x * 128;
    int m0w = (wid & 1) * 64;
    int n0w = (wid >> 1) * 32;

    float acc[4][4][4];
#pragma unroll
    for (int i = 0; i < 4; i++)
#pragma unroll
        for (int j = 0; j < 4; j++)
#pragma unroll
            for (int v = 0; v < 4; v++) acc[i][j][v] = 0.f;

    uint32_t smb = (uint32_t)__cvta_generic_to_shared(hsm);
    // per-thread load: 4 chunks of 16B. Total chunks = 1024:
    // A tile 128x32 halfs = 512 chunks, B tile = 512 chunks.
    // chunk c in [0,1024): tile = c>>9, cc = c&511, row = cc>>2, q = cc&3
#define HLOAD(K0, ST)                                                             \
    do {                                                                          \
        uint32_t sb = smb + (ST) * HSTAGE_H * 2;                                  \
        _Pragma("unroll")                                                         \
        for (int j = 0; j < 4; j++) {                                             \
            int c = tid + j * 256;                                                \
            int tile = c >> 9, cc = c & 511, row = cc >> 2, q = cc & 3;           \
            const __half* gp = tile ? (Bt + (size_t)(n0 + row) * K + (K0) + q * 8)\
                                    : (A + (size_t)(m0 + row) * K + (K0) + q * 8);\
            uint32_t sp = sb + (uint32_t)(tile * 128 * HAST + row * HAST + q * 8) * 2; \
            asm volatile("cp.async.ca.shared.global [%0], [%1], 16;\n" ::         \
                "r"(sp), "l"(gp));                                                \
        }                                                                         \
    } while (0)

    int KT = K >> 5;
    HLOAD(0, 0);
    asm volatile("cp.async.commit_group;\n");

    for (int kt = 0; kt < KT; kt++) {
        if (kt + 1 < KT) {
            HLOAD((kt + 1) << 5, (kt + 1) & 1);
            asm volatile("cp.async.commit_group;\n");
            asm volatile("cp.async.wait_group 1;\n");
        } else {
            asm volatile("cp.async.wait_group 0;\n");
        }
        __syncthreads();
        const __half* as = hsm + (kt & 1) * HSTAGE_H;
        const __half* bs = as + 128 * HAST;
#pragma unroll
        for (int ks = 0; ks < 2; ks++) {
            int kk = ks * 16;
            uint32_t af[4][4], bf[4][2];
#pragma unroll
            for (int mi = 0; mi < 4; mi++) {
                const __half* ap = as + (m0w + mi * 16 + g) * HAST + kk + 2 * tig;
                af[mi][0] = *(const uint32_t*)(ap);
                af[mi][1] = *(const uint32_t*)(ap + 8 * HAST);
                af[mi][2] = *(const uint32_t*)(ap + 8);
                af[mi][3] = *(const uint32_t*)(ap + 8 * HAST + 8);
            }
#pragma unroll
            for (int ni = 0; ni < 4; ni++) {
                const __half* bp = bs + (n0w + ni * 8 + g) * HAST + kk + 2 * tig;
                bf[ni][0] = *(const uint32_t*)(bp);
                bf[ni][1] = *(const uint32_t*)(bp + 8);
            }
#pragma unroll
            for (int mi = 0; mi < 4; mi++)
#pragma unroll
                for (int ni = 0; ni < 4; ni++) {
                    asm volatile(
                        "mma.sync.aligned.m16n8k16.row.col.f32.f16.f16.f32 "
                        "{%0,%1,%2,%3}, {%4,%5,%6,%7}, {%8,%9}, {%0,%1,%2,%3};\n"
                        : "+f"(acc[mi][ni][0]), "+f"(acc[mi][ni][1]),
                          "+f"(acc[mi][ni][2]), "+f"(acc[mi][ni][3])
                        : "r"(af[mi][0]), "r"(af[mi][1]), "r"(af[mi][2]), "r"(af[mi][3]),
                          "r"(bf[ni][0]), "r"(bf[ni][1]));
                }
        }
        __syncthreads();
    }

#pragma unroll
    for (int mi = 0; mi < 4; mi++) {
        int r0 = m0 + m0w + mi * 16 + g;
#pragma unroll
        for (int ni = 0; ni < 4; ni++) {
            int c = n0 + n0w + ni * 8 + 2 * tig;
            float b0 = bias[c], b1 = bias[c + 1];
            float v0 = acc[mi][ni][0] + b0;
            float v1 = acc[mi][ni][1] + b1;
            float v2 = acc[mi][ni][2] + b0;
            float v3 = acc[mi][ni][3] + b1;
            if (EPI == 0) {
                v0 = fmaxf(v0, 0.f); v1 = fmaxf(v1, 0.f);
                v2 = fmaxf(v2, 0.f); v3 = fmaxf(v3, 0.f);
                __half2 h01 = __floats2half2_rn(v0, v1);
                __half2 h23 = __floats2half2_rn(v2, v3);
                *(__half2*)&C16[(size_t)r0 * N + c] = h01;
                *(__half2*)&C16[(size_t)(r0 + 8) * N + c] = h23;
            } else {
                v0 += resid[(size_t)r0 * N + c];
                v1 += resid[(size_t)r0 * N + c + 1];
                v2 += resid[(size_t)(r0 + 8) * N + c];
                v3 += resid[(size_t)(r0 + 8) * N + c + 1];
                *(float2*)&C32[(size_t)r0 * N + c] = make_float2(v0, v1);
                *(float2*)&C32[(size_t)(r0 + 8) * N + c] = make_float2(v2, v3);
            }
        }
    }
#undef HLOAD
}

// ---------------------------------------------------------------------------
extern "C" void kernel_launch(void* const* d_in, const int* in_sizes, int n_in,
                              void* d_out, int out_size)
{
    const float* tgt    = (const float*)d_in[0];
    const float* memory = (const float*)d_in[1];
    const float* sa_w   = (const float*)d_in[4];
    const float* sa_b   = (const float*)d_in[5];
    const float* mha_w  = (const float*)d_in[6];
    const float* mha_b  = (const float*)d_in[7];
    const float* ff_w1  = (const float*)d_in[8];
    const float* ff_b1  = (const float*)d_in[9];
    const float* ff_w2  = (const float*)d_in[10];
    const float* ff_b2  = (const float*)d_in[11];
    const float* ln1g   = (const float*)d_in[12];
    const float* ln1b   = (const float*)d_in[13];
    const float* ln2g   = (const float*)d_in[14];
    const float* ln2b   = (const float*)d_in[15];
    const float* ln3g   = (const float*)d_in[16];
    const float* ln3b   = (const float*)d_in[17];
    float* out = (float*)d_out;

    float *h, *attn, *x1;
    __half *h16, *mid16, *w1t, *w2t;
    cudaGetSymbolAddress((void**)&h,     g_h);
    cudaGetSymbolAddress((void**)&attn,  g_attn);
    cudaGetSymbolAddress((void**)&x1,    g_x1);
    cudaGetSymbolAddress((void**)&h16,   g_h16);
    cudaGetSymbolAddress((void**)&mid16, g_mid16);
    cudaGetSymbolAddress((void**)&w1t,   g_w1t);
    cudaGetSymbolAddress((void**)&w2t,   g_w2t);

    cudaFuncSetAttribute(attn_tc, cudaFuncAttributeMaxDynamicSharedMemorySize, ATTN_SMEM);
    cudaFuncSetAttribute(hgemm<0>, cudaFuncAttributeMaxDynamicSharedMemorySize, HGEMM_SMEM);
    cudaFuncSetAttribute(hgemm<1>, cudaFuncAttributeMaxDynamicSharedMemorySize, HGEMM_SMEM);

    dim3 attn_grid(BATCH * NHEAD, SEQ / 128);
    dim3 gfc(DMODEL / 128, MROWS / 128);     // (8, 32)
    dim3 gff1(DFF / 128, MROWS / 128);       // (32, 32)

    // prep: transpose+convert FFN weights to fp16 (~20 us)
    wcvt_kernel<<<dim3(DFF / 32, DMODEL / 32), 256>>>(ff_w1, w1t, DMODEL, DFF);
    wcvt_kernel<<<dim3(DMODEL / 32, DFF / 32), 256>>>(ff_w2, w2t, DFF, DMODEL);

    // ---- self-attention block ----
    ln_kernel<0><<<MROWS, 256>>>(tgt, ln1g, ln1b, h, nullptr);
    attn_tc<<<attn_grid, 256, ATTN_SMEM>>>(h, h, h, attn);
    gemm_tc<false, true><<<gfc, 256>>>(attn, sa_w, sa_b, tgt, x1,
                                       MROWS, DMODEL, DMODEL);
    // ---- cross-attention block (Q=K=memory, V=LN2(x)) ----
    ln_kernel<0><<<MROWS, 256>>>(x1, ln2g, ln2b, h, nullptr);
    attn_tc<<<attn_grid, 256, ATTN_SMEM>>>(memory, memory, h, attn);
    gemm_tc<false, true><<<gfc, 256>>>(attn, mha_w, mha_b, x1, out,
                                       MROWS, DMODEL, DMODEL);
    // ---- FFN block (fp16 tensor cores) ----
    ln_kernel<1><<<MROWS, 256>>>(out, ln3g, ln3b, nullptr, h16);
    hgemm<0><<<gff1, 256, HGEMM_SMEM>>>(h16, w1t, ff_b1, nullptr,
                                        mid16, nullptr, MROWS, DFF, DMODEL);
    hgemm<1><<<gfc, 256, HGEMM_SMEM>>>(mid16, w2t, ff_b2, out,
                                       nullptr, out, MROWS, DMODEL, DFF);
}

// round 9
// speedup vs baseline: 1.6516x; 1.2108x over previous
#include <cuda_runtime.h>
#include <cuda_fp16.h>
#include <math.h>
#include <stdint.h>

#define BATCH 4
#define SEQ 1024
#define DMODEL 1024
#define NHEAD 16
#define DHEAD 64
#define DFF 4096
#define MROWS (BATCH * SEQ)

__device__ float g_h[MROWS * DMODEL];          // LN out (fp32)
__device__ float g_x1[MROWS * DMODEL];         // residual stream
__device__ __half g_attn16[MROWS * DMODEL];    // attention out (fp16)
__device__ __half g_h16[MROWS * DMODEL];       // LN3 out (fp16)
__device__ __half g_mid16[MROWS * DFF];        // FFN hidden (fp16)
__device__ __half g_wsat[DMODEL * DMODEL];     // sa_w^T fp16
__device__ __half g_wmhat[DMODEL * DMODEL];    // mha_w^T fp16
__device__ __half g_w1t[DFF * DMODEL];         // ff_w1^T fp16
__device__ __half g_w2t[DMODEL * DFF];         // ff_w2^T fp16

// ---------------------------------------------------------------------------
// LayerNorm (F16OUT=1 writes __half)
// ---------------------------------------------------------------------------
template <int F16OUT>
__global__ __launch_bounds__(256) void ln_kernel(
    const float* __restrict__ x, const float* __restrict__ gam,
    const float* __restrict__ bet, float* __restrict__ out,
    __half* __restrict__ out16)
{
    int row = blockIdx.x;
    const float* xr = x + (size_t)row * DMODEL;
    float v[4];
    float s = 0.f, s2 = 0.f;
#pragma unroll
    for (int i = 0; i < 4; i++) {
        v[i] = xr[threadIdx.x + i * 256];
        s += v[i];
        s2 += v[i] * v[i];
    }
#pragma unroll
    for (int o = 16; o; o >>= 1) {
        s  += __shfl_xor_sync(0xffffffffu, s, o);
        s2 += __shfl_xor_sync(0xffffffffu, s2, o);
    }
    __shared__ float red[2][8];
    int w = threadIdx.x >> 5, l = threadIdx.x & 31;
    if (l == 0) { red[0][w] = s; red[1][w] = s2; }
    __syncthreads();
    s = 0.f; s2 = 0.f;
#pragma unroll
    for (int i = 0; i < 8; i++) { s += red[0][i]; s2 += red[1][i]; }
    float mean = s * (1.0f / DMODEL);
    float var  = s2 * (1.0f / DMODEL) - mean * mean;
    float rstd = rsqrtf(var + 1e-5f);
#pragma unroll
    for (int i = 0; i < 4; i++) {
        int c = threadIdx.x + i * 256;
        float y = (v[i] - mean) * rstd * gam[c] + bet[c];
        if (F16OUT) out16[(size_t)row * DMODEL + c] = __float2half_rn(y);
        else        out[(size_t)row * DMODEL + c] = y;
    }
}

// ---------------------------------------------------------------------------
// Weight transpose+convert: W[K,N] fp32 -> Wt[N,K] fp16
// ---------------------------------------------------------------------------
__global__ __launch_bounds__(256) void wcvt_kernel(
    const float* __restrict__ W, __half* __restrict__ Wt, int K, int N)
{
    __shared__ float tile[32][33];
    int k0 = blockIdx.y * 32, n0 = blockIdx.x * 32;
    int tx = threadIdx.x & 31, ty = threadIdx.x >> 5;
#pragma unroll
    for (int j = 0; j < 4; j++)
        tile[ty + 8 * j][tx] = W[(size_t)(k0 + ty + 8 * j) * N + n0 + tx];
    __syncthreads();
#pragma unroll
    for (int j = 0; j < 4; j++) {
        int n = n0 + ty + 8 * j, k = k0 + tx;
        Wt[(size_t)n * K + k] = __float2half_rn(tile[tx][ty + 8 * j]);
    }
}

// ---------------------------------------------------------------------------
// FP16 flash attention. fp32 inputs (converted on load), fp16 output.
// Block: 128 q-rows, 8 warps (16 rows each), k-tiles of 64 keys.
// m16n8k16 fp32-acc. Smem (half): Ps[128][72] (Q then P), Ks[64][72],
// Vs[64][72] transposed [d][key]. Stride 72: frag bank = 4g+tig, distinct.
// ---------------------------------------------------------------------------
#define PST2 72
#define KST2 72
#define VST2 72
#define ATTN_SMEM ((128 * PST2 + 64 * KST2 + 64 * VST2) * 2)

__global__ __launch_bounds__(256) void attn_h(
    const float* __restrict__ Qb, const float* __restrict__ Kb,
    const float* __restrict__ Vb, __half* __restrict__ Ob)
{
    extern __shared__ __half hsm[];
    __half* Ps = hsm;
    __half* Ks = Ps + 128 * PST2;
    __half* Vs = Ks + 64 * KST2;

    int bh = blockIdx.x;
    int b = bh >> 4, h = bh & 15;
    int q0 = blockIdx.y << 7;
    int t = threadIdx.x, w = t >> 5, lane = t & 31;
    int g = lane >> 2, tig = lane & 3;
    int qrow = w * 16 + g;

    size_t base = ((size_t)b * SEQ) * DMODEL + (size_t)h * DHEAD;
    const float* Qp = Qb + base;
    const float* Kp = Kb + base;
    const float* Vp = Vb + base;

    // Stage Q (scaled by 1/8) as fp16
    for (int i = t; i < 128 * 16; i += 256) {
        int r = i >> 4, c4 = (i & 15) * 4;
        float4 v = *(const float4*)&Qp[(size_t)(q0 + r) * DMODEL + c4];
        *(__half2*)&Ps[r * PST2 + c4]     = __floats2half2_rn(v.x * 0.125f, v.y * 0.125f);
        *(__half2*)&Ps[r * PST2 + c4 + 2] = __floats2half2_rn(v.z * 0.125f, v.w * 0.125f);
    }
    __syncthreads();

    // Q fragments: 4 k16-steps x 4 regs
    uint32_t qf[4][4];
#pragma unroll
    for (int ks = 0; ks < 4; ks++) {
        int kk = ks * 16;
        qf[ks][0] = *(const uint32_t*)&Ps[qrow * PST2 + kk + 2 * tig];
        qf[ks][1] = *(const uint32_t*)&Ps[(qrow + 8) * PST2 + kk + 2 * tig];
        qf[ks][2] = *(const uint32_t*)&Ps[qrow * PST2 + kk + 2 * tig + 8];
        qf[ks][3] = *(const uint32_t*)&Ps[(qrow + 8) * PST2 + kk + 2 * tig + 8];
    }

    float oacc[8][4];
#pragma unroll
    for (int i = 0; i < 8; i++)
#pragma unroll
        for (int v = 0; v < 4; v++) oacc[i][v] = 0.f;
    float m_lo = -3.4e38f, m_hi = -3.4e38f, l_lo = 0.f, l_hi = 0.f;
    __syncthreads();   // Ps now reusable for P

    for (int kt = 0; kt < SEQ / 64; kt++) {
        int k0 = kt << 6;
        for (int i = t; i < 64 * 16; i += 256) {
            int r = i >> 4, c4 = (i & 15) * 4;
            float4 kv = *(const float4*)&Kp[(size_t)(k0 + r) * DMODEL + c4];
            *(__half2*)&Ks[r * KST2 + c4]     = __floats2half2_rn(kv.x, kv.y);
            *(__half2*)&Ks[r * KST2 + c4 + 2] = __floats2half2_rn(kv.z, kv.w);
            float4 vv = *(const float4*)&Vp[(size_t)(k0 + r) * DMODEL + c4];
            Vs[(c4 + 0) * VST2 + r] = __float2half_rn(vv.x);
            Vs[(c4 + 1) * VST2 + r] = __float2half_rn(vv.y);
            Vs[(c4 + 2) * VST2 + r] = __float2half_rn(vv.z);
            Vs[(c4 + 3) * VST2 + r] = __float2half_rn(vv.w);
        }
        __syncthreads();

        // ---- S = Q @ K^T ----
        float sacc[8][4];
#pragma unroll
        for (int i = 0; i < 8; i++)
#pragma unroll
            for (int v = 0; v < 4; v++) sacc[i][v] = 0.f;
#pragma unroll
        for (int ks = 0; ks < 4; ks++) {
            int kk = ks * 16;
#pragma unroll
            for (int ni = 0; ni < 8; ni++) {
                const __half* bp = Ks + (ni * 8 + g) * KST2 + kk + 2 * tig;
                uint32_t b0 = *(const uint32_t*)(bp);
                uint32_t b1 = *(const uint32_t*)(bp + 8);
                asm volatile(
                    "mma.sync.aligned.m16n8k16.row.col.f32.f16.f16.f32 "
                    "{%0,%1,%2,%3}, {%4,%5,%6,%7}, {%8,%9}, {%0,%1,%2,%3};\n"
                    : "+f"(sacc[ni][0]), "+f"(sacc[ni][1]),
                      "+f"(sacc[ni][2]), "+f"(sacc[ni][3])
                    : "r"(qf[ks][0]), "r"(qf[ks][1]), "r"(qf[ks][2]), "r"(qf[ks][3]),
                      "r"(b0), "r"(b1));
            }
        }

        // ---- online softmax ----
        float tl = -3.4e38f, th = -3.4e38f;
#pragma unroll
        for (int ni = 0; ni < 8; ni++) {
            tl = fmaxf(tl, fmaxf(sacc[ni][0], sacc[ni][1]));
            th = fmaxf(th, fmaxf(sacc[ni][2], sacc[ni][3]));
        }
        tl = fmaxf(tl, __shfl_xor_sync(0xffffffffu, tl, 1));
        tl = fmaxf(tl, __shfl_xor_sync(0xffffffffu, tl, 2));
        th = fmaxf(th, __shfl_xor_sync(0xffffffffu, th, 1));
        th = fmaxf(th, __shfl_xor_sync(0xffffffffu, th, 2));
        float nm_lo = fmaxf(m_lo, tl), nm_hi = fmaxf(m_hi, th);
        float corr_lo = __expf(m_lo - nm_lo), corr_hi = __expf(m_hi - nm_hi);
        m_lo = nm_lo; m_hi = nm_hi;

        float sum_lo = 0.f, sum_hi = 0.f;
#pragma unroll
        for (int ni = 0; ni < 8; ni++) {
            float e0 = __expf(sacc[ni][0] - nm_lo);
            float e1 = __expf(sacc[ni][1] - nm_lo);
            float e2 = __expf(sacc[ni][2] - nm_hi);
            float e3 = __expf(sacc[ni][3] - nm_hi);
            sum_lo += e0 + e1; sum_hi += e2 + e3;
            int c = ni * 8 + 2 * tig;
            *(__half2*)&Ps[qrow * PST2 + c]       = __floats2half2_rn(e0, e1);
            *(__half2*)&Ps[(qrow + 8) * PST2 + c] = __floats2half2_rn(e2, e3);
        }
        sum_lo += __shfl_xor_sync(0xffffffffu, sum_lo, 1);
        sum_lo += __shfl_xor_sync(0xffffffffu, sum_lo, 2);
        sum_hi += __shfl_xor_sync(0xffffffffu, sum_hi, 1);
        sum_hi += __shfl_xor_sync(0xffffffffu, sum_hi, 2);
        l_lo = l_lo * corr_lo + sum_lo;
        l_hi = l_hi * corr_hi + sum_hi;

#pragma unroll
        for (int ni = 0; ni < 8; ni++) {
            oacc[ni][0] *= corr_lo; oacc[ni][1] *= corr_lo;
            oacc[ni][2] *= corr_hi; oacc[ni][3] *= corr_hi;
        }
        __syncwarp();   // P rows are warp-local

        // ---- O += P @ V (V transposed in smem) ----
#pragma unroll
        for (int ks = 0; ks < 4; ks++) {
            int kk = ks * 16;
            uint32_t pa0 = *(const uint32_t*)&Ps[qrow * PST2 + kk + 2 * tig];
            uint32_t pa1 = *(const uint32_t*)&Ps[(qrow + 8) * PST2 + kk + 2 * tig];
            uint32_t pa2 = *(const uint32_t*)&Ps[qrow * PST2 + kk + 2 * tig + 8];
            uint32_t pa3 = *(const uint32_t*)&Ps[(qrow + 8) * PST2 + kk + 2 * tig + 8];
#pragma unroll
            for (int ni = 0; ni < 8; ni++) {
                const __half* bp = Vs + (ni * 8 + g) * VST2 + kk + 2 * tig;
                uint32_t b0 = *(const uint32_t*)(bp);
                uint32_t b1 = *(const uint32_t*)(bp + 8);
                asm volatile(
                    "mma.sync.aligned.m16n8k16.row.col.f32.f16.f16.f32 "
                    "{%0,%1,%2,%3}, {%4,%5,%6,%7}, {%8,%9}, {%0,%1,%2,%3};\n"
                    : "+f"(oacc[ni][0]), "+f"(oacc[ni][1]),
                      "+f"(oacc[ni][2]), "+f"(oacc[ni][3])
                    : "r"(pa0), "r"(pa1), "r"(pa2), "r"(pa3),
                      "r"(b0), "r"(b1));
            }
        }
        __syncthreads();
    }

    float inv_lo = 1.f / l_lo, inv_hi = 1.f / l_hi;
    __half* Op = Ob + base;
#pragma unroll
    for (int ni = 0; ni < 8; ni++) {
        int c = ni * 8 + 2 * tig;
        *(__half2*)&Op[(size_t)(q0 + qrow) * DMODEL + c] =
            __floats2half2_rn(oacc[ni][0] * inv_lo, oacc[ni][1] * inv_lo);
        *(__half2*)&Op[(size_t)(q0 + qrow + 8) * DMODEL + c] =
            __floats2half2_rn(oacc[ni][2] * inv_hi, oacc[ni][3] * inv_hi);
    }
}

// ---------------------------------------------------------------------------
// FP16 GEMM: A[M,K] fp16, Bt[N,K] fp16. 128x128x32, 2-stage, m16n8k16.
// EPI 0: fp16 out = relu(acc+bias).  EPI 1: fp32 out = acc+bias+resid.
// ---------------------------------------------------------------------------
#define HAST 56
#define HSTAGE_H (2 * 128 * HAST)
#define HGEMM_SMEM (2 * HSTAGE_H * 2)

template <int EPI>
__global__ __launch_bounds__(256) void hgemm(
    const __half* __restrict__ A, const __half* __restrict__ Bt,
    const float* __restrict__ bias, const float* __restrict__ resid,
    __half* __restrict__ C16, float* __restrict__ C32, int M, int N, int K)
{
    extern __shared__ __half hsm[];

    int tid = threadIdx.x;
    int wid = tid >> 5;
    int lane = tid & 31;
    int g = lane >> 2;
    int tig = lane & 3;
    int m0 = blockIdx.y * 128, n0 = blockIdx.x * 128;
    int m0w = (wid & 1) * 64;
    int n0w = (wid >> 1) * 32;

    float acc[4][4][4];
#pragma unroll
    for (int i = 0; i < 4; i++)
#pragma unroll
        for (int j = 0; j < 4; j++)
#pragma unroll
            for (int v = 0; v < 4; v++) acc[i][j][v] = 0.f;

    uint32_t smb = (uint32_t)__cvta_generic_to_shared(hsm);
#define HLOAD(K0, ST)                                                             \
    do {                                                                          \
        uint32_t sb = smb + (ST) * HSTAGE_H * 2;                                  \
        _Pragma("unroll")                                                         \
        for (int j = 0; j < 4; j++) {                                             \
            int c = tid + j * 256;                                                \
            int tile = c >> 9, cc = c & 511, row = cc >> 2, q = cc & 3;           \
            const __half* gp = tile ? (Bt + (size_t)(n0 + row) * K + (K0) + q * 8)\
                                    : (A + (size_t)(m0 + row) * K + (K0) + q * 8);\
            uint32_t sp = sb + (uint32_t)(tile * 128 * HAST + row * HAST + q * 8) * 2; \
            asm volatile("cp.async.ca.shared.global [%0], [%1], 16;\n" ::         \
                "r"(sp), "l"(gp));                                                \
        }                                                                         \
    } while (0)

    int KT = K >> 5;
    HLOAD(0, 0);
    asm volatile("cp.async.commit_group;\n");

    for (int kt = 0; kt < KT; kt++) {
        if (kt + 1 < KT) {
            HLOAD((kt + 1) << 5, (kt + 1) & 1);
            asm volatile("cp.async.commit_group;\n");
            asm volatile("cp.async.wait_group 1;\n");
        } else {
            asm volatile("cp.async.wait_group 0;\n");
        }
        __syncthreads();
        const __half* as = hsm + (kt & 1) * HSTAGE_H;
        const __half* bs = as + 128 * HAST;
#pragma unroll
        for (int ks = 0; ks < 2; ks++) {
            int kk = ks * 16;
            uint32_t af[4][4], bf[4][2];
#pragma unroll
            for (int mi = 0; mi < 4; mi++) {
                const __half* ap = as + (m0w + mi * 16 + g) * HAST + kk + 2 * tig;
                af[mi][0] = *(const uint32_t*)(ap);
                af[mi][1] = *(const uint32_t*)(ap + 8 * HAST);
                af[mi][2] = *(const uint32_t*)(ap + 8);
                af[mi][3] = *(const uint32_t*)(ap + 8 * HAST + 8);
            }
#pragma unroll
            for (int ni = 0; ni < 4; ni++) {
                const __half* bp = bs + (n0w + ni * 8 + g) * HAST + kk + 2 * tig;
                bf[ni][0] = *(const uint32_t*)(bp);
                bf[ni][1] = *(const uint32_t*)(bp + 8);
            }
#pragma unroll
            for (int mi = 0; mi < 4; mi++)
#pragma unroll
                for (int ni = 0; ni < 4; ni++) {
                    asm volatile(
                        "mma.sync.aligned.m16n8k16.row.col.f32.f16.f16.f32 "
                        "{%0,%1,%2,%3}, {%4,%5,%6,%7}, {%8,%9}, {%0,%1,%2,%3};\n"
                        : "+f"(acc[mi][ni][0]), "+f"(acc[mi][ni][1]),
                          "+f"(acc[mi][ni][2]), "+f"(acc[mi][ni][3])
                        : "r"(af[mi][0]), "r"(af[mi][1]), "r"(af[mi][2]), "r"(af[mi][3]),
                          "r"(bf[ni][0]), "r"(bf[ni][1]));
                }
        }
        __syncthreads();
    }

#pragma unroll
    for (int mi = 0; mi < 4; mi++) {
        int r0 = m0 + m0w + mi * 16 + g;
#pragma unroll
        for (int ni = 0; ni < 4; ni++) {
            int c = n0 + n0w + ni * 8 + 2 * tig;
            float b0 = bias[c], b1 = bias[c + 1];
            float v0 = acc[mi][ni][0] + b0;
            float v1 = acc[mi][ni][1] + b1;
            float v2 = acc[mi][ni][2] + b0;
            float v3 = acc[mi][ni][3] + b1;
            if (EPI == 0) {
                v0 = fmaxf(v0, 0.f); v1 = fmaxf(v1, 0.f);
                v2 = fmaxf(v2, 0.f); v3 = fmaxf(v3, 0.f);
                *(__half2*)&C16[(size_t)r0 * N + c] = __floats2half2_rn(v0, v1);
                *(__half2*)&C16[(size_t)(r0 + 8) * N + c] = __floats2half2_rn(v2, v3);
            } else {
                v0 += resid[(size_t)r0 * N + c];
                v1 += resid[(size_t)r0 * N + c + 1];
                v2 += resid[(size_t)(r0 + 8) * N + c];
                v3 += resid[(size_t)(r0 + 8) * N + c + 1];
                *(float2*)&C32[(size_t)r0 * N + c] = make_float2(v0, v1);
                *(float2*)&C32[(size_t)(r0 + 8) * N + c] = make_float2(v2, v3);
            }
        }
    }
#undef HLOAD
}

// ---------------------------------------------------------------------------
extern "C" void kernel_launch(void* const* d_in, const int* in_sizes, int n_in,
                              void* d_out, int out_size)
{
    const float* tgt    = (const float*)d_in[0];
    const float* memory = (const float*)d_in[1];
    const float* sa_w   = (const float*)d_in[4];
    const float* sa_b   = (const float*)d_in[5];
    const float* mha_w  = (const float*)d_in[6];
    const float* mha_b  = (const float*)d_in[7];
    const float* ff_w1  = (const float*)d_in[8];
    const float* ff_b1  = (const float*)d_in[9];
    const float* ff_w2  = (const float*)d_in[10];
    const float* ff_b2  = (const float*)d_in[11];
    const float* ln1g   = (const float*)d_in[12];
    const float* ln1b   = (const float*)d_in[13];
    const float* ln2g   = (const float*)d_in[14];
    const float* ln2b   = (const float*)d_in[15];
    const float* ln3g   = (const float*)d_in[16];
    const float* ln3b   = (const float*)d_in[17];
    float* out = (float*)d_out;

    float *h, *x1;
    __half *attn16, *h16, *mid16, *wsat, *wmhat, *w1t, *w2t;
    cudaGetSymbolAddress((void**)&h,      g_h);
    cudaGetSymbolAddress((void**)&x1,     g_x1);
    cudaGetSymbolAddress((void**)&attn16, g_attn16);
    cudaGetSymbolAddress((void**)&h16,    g_h16);
    cudaGetSymbolAddress((void**)&mid16,  g_mid16);
    cudaGetSymbolAddress((void**)&wsat,   g_wsat);
    cudaGetSymbolAddress((void**)&wmhat,  g_wmhat);
    cudaGetSymbolAddress((void**)&w1t,    g_w1t);
    cudaGetSymbolAddress((void**)&w2t,    g_w2t);

    cudaFuncSetAttribute(attn_h, cudaFuncAttributeMaxDynamicSharedMemorySize, ATTN_SMEM);
    cudaFuncSetAttribute(hgemm<0>, cudaFuncAttributeMaxDynamicSharedMemorySize, HGEMM_SMEM);
    cudaFuncSetAttribute(hgemm<1>, cudaFuncAttributeMaxDynamicSharedMemorySize, HGEMM_SMEM);

    dim3 attn_grid(BATCH * NHEAD, SEQ / 128);
    dim3 gfc(DMODEL / 128, MROWS / 128);     // (8, 32)
    dim3 gff1(DFF / 128, MROWS / 128);       // (32, 32)

    // prep: transpose+convert all weights to fp16
    wcvt_kernel<<<dim3(DMODEL / 32, DMODEL / 32), 256>>>(sa_w, wsat, DMODEL, DMODEL);
    wcvt_kernel<<<dim3(DMODEL / 32, DMODEL / 32), 256>>>(mha_w, wmhat, DMODEL, DMODEL);
    wcvt_kernel<<<dim3(DFF / 32, DMODEL / 32), 256>>>(ff_w1, w1t, DMODEL, DFF);
    wcvt_kernel<<<dim3(DMODEL / 32, DFF / 32), 256>>>(ff_w2, w2t, DFF, DMODEL);

    // ---- self-attention block ----
    ln_kernel<0><<<MROWS, 256>>>(tgt, ln1g, ln1b, h, nullptr);
    attn_h<<<attn_grid, 256, ATTN_SMEM>>>(h, h, h, attn16);
    hgemm<1><<<gfc, 256, HGEMM_SMEM>>>(attn16, wsat, sa_b, tgt,
                                       nullptr, x1, MROWS, DMODEL, DMODEL);
    // ---- cross-attention block (Q=K=memory, V=LN2(x)) ----
    ln_kernel<0><<<MROWS, 256>>>(x1, ln2g, ln2b, h, nullptr);
    attn_h<<<attn_grid, 256, ATTN_SMEM>>>(memory, memory, h, attn16);
    hgemm<1><<<gfc, 256, HGEMM_SMEM>>>(attn16, wmhat, mha_b, x1,
                                       nullptr, out, MROWS, DMODEL, DMODEL);
    // ---- FFN block ----
    ln_kernel<1><<<MROWS, 256>>>(out, ln3g, ln3b, nullptr, h16);
    hgemm<0><<<gff1, 256, HGEMM_SMEM>>>(h16, w1t, ff_b1, nullptr,
                                        mid16, nullptr, MROWS, DFF, DMODEL);
    hgemm<1><<<gfc, 256, HGEMM_SMEM>>>(mid16, w2t, ff_b2, out,
                                       nullptr, out, MROWS, DMODEL, DFF);
}

// round 10
// speedup vs baseline: 1.6699x; 1.0111x over previous
#include <cuda_runtime.h>
#include <cuda_fp16.h>
#include <math.h>
#include <stdint.h>

#define BATCH 4
#define SEQ 1024
#define DMODEL 1024
#define NHEAD 16
#define DHEAD 64
#define DFF 4096
#define MROWS (BATCH * SEQ)

__device__ float g_h[MROWS * DMODEL];          // LN out (fp32) [unused now, kept small set]
__device__ float g_x1[MROWS * DMODEL];         // residual stream
__device__ __half g_attn16[MROWS * DMODEL];    // attention out (fp16)
__device__ __half g_h16[MROWS * DMODEL];       // LN out (fp16)
__device__ __half g_mem16[MROWS * DMODEL];     // memory (fp16)
__device__ __half g_mid16[MROWS * DFF];        // FFN hidden (fp16)
__device__ __half g_wsat[DMODEL * DMODEL];     // sa_w^T fp16
__device__ __half g_wmhat[DMODEL * DMODEL];    // mha_w^T fp16
__device__ __half g_w1t[DFF * DMODEL];         // ff_w1^T fp16
__device__ __half g_w2t[DMODEL * DFF];         // ff_w2^T fp16

// ---------------------------------------------------------------------------
// fp32 -> fp16 convert (no transpose), float4 vectorized
// ---------------------------------------------------------------------------
__global__ __launch_bounds__(256) void cvt16_kernel(
    const float* __restrict__ in, __half* __restrict__ out, int n4)
{
    int i = blockIdx.x * 256 + threadIdx.x;
    if (i < n4) {
        float4 v = ((const float4*)in)[i];
        __half2 a = __floats2half2_rn(v.x, v.y);
        __half2 b = __floats2half2_rn(v.z, v.w);
        ((__half2*)out)[2 * i]     = a;
        ((__half2*)out)[2 * i + 1] = b;
    }
}

// ---------------------------------------------------------------------------
// LayerNorm -> fp16 out
// ---------------------------------------------------------------------------
__global__ __launch_bounds__(256) void ln_kernel(
    const float* __restrict__ x, const float* __restrict__ gam,
    const float* __restrict__ bet, __half* __restrict__ out16)
{
    int row = blockIdx.x;
    const float* xr = x + (size_t)row * DMODEL;
    float v[4];
    float s = 0.f, s2 = 0.f;
#pragma unroll
    for (int i = 0; i < 4; i++) {
        v[i] = xr[threadIdx.x + i * 256];
        s += v[i];
        s2 += v[i] * v[i];
    }
#pragma unroll
    for (int o = 16; o; o >>= 1) {
        s  += __shfl_xor_sync(0xffffffffu, s, o);
        s2 += __shfl_xor_sync(0xffffffffu, s2, o);
    }
    __shared__ float red[2][8];
    int w = threadIdx.x >> 5, l = threadIdx.x & 31;
    if (l == 0) { red[0][w] = s; red[1][w] = s2; }
    __syncthreads();
    s = 0.f; s2 = 0.f;
#pragma unroll
    for (int i = 0; i < 8; i++) { s += red[0][i]; s2 += red[1][i]; }
    float mean = s * (1.0f / DMODEL);
    float var  = s2 * (1.0f / DMODEL) - mean * mean;
    float rstd = rsqrtf(var + 1e-5f);
#pragma unroll
    for (int i = 0; i < 4; i++) {
        int c = threadIdx.x + i * 256;
        float y = (v[i] - mean) * rstd * gam[c] + bet[c];
        out16[(size_t)row * DMODEL + c] = __float2half_rn(y);
    }
}

// ---------------------------------------------------------------------------
// Weight transpose+convert: W[K,N] fp32 -> Wt[N,K] fp16
// ---------------------------------------------------------------------------
__global__ __launch_bounds__(256) void wcvt_kernel(
    const float* __restrict__ W, __half* __restrict__ Wt, int K, int N)
{
    __shared__ float tile[32][33];
    int k0 = blockIdx.y * 32, n0 = blockIdx.x * 32;
    int tx = threadIdx.x & 31, ty = threadIdx.x >> 5;
#pragma unroll
    for (int j = 0; j < 4; j++)
        tile[ty + 8 * j][tx] = W[(size_t)(k0 + ty + 8 * j) * N + n0 + tx];
    __syncthreads();
#pragma unroll
    for (int j = 0; j < 4; j++) {
        int n = n0 + ty + 8 * j, k = k0 + tx;
        Wt[(size_t)n * K + k] = __float2half_rn(tile[tx][ty + 8 * j]);
    }
}

// ---------------------------------------------------------------------------
// FP16 flash attention, fp16 in / fp16 out.
// Block 128 q-rows, 8 warps, k-tiles 64. Smem strides 72 halfs.
// ---------------------------------------------------------------------------
#define PST2 72
#define KST2 72
#define VST2 72
#define ATTN_SMEM ((128 * PST2 + 64 * KST2 + 64 * VST2) * 2)

__global__ __launch_bounds__(256) void attn_h(
    const __half* __restrict__ Qb, const __half* __restrict__ Kb,
    const __half* __restrict__ Vb, __half* __restrict__ Ob)
{
    extern __shared__ __half hsm[];
    __half* Ps = hsm;
    __half* Ks = Ps + 128 * PST2;
    __half* Vs = Ks + 64 * KST2;

    int bh = blockIdx.x;
    int b = bh >> 4, h = bh & 15;
    int q0 = blockIdx.y << 7;
    int t = threadIdx.x, w = t >> 5, lane = t & 31;
    int g = lane >> 2, tig = lane & 3;
    int qrow = w * 16 + g;

    size_t base = ((size_t)b * SEQ) * DMODEL + (size_t)h * DHEAD;
    const __half* Qp = Qb + base;
    const __half* Kp = Kb + base;
    const __half* Vp = Vb + base;

    // Stage Q (scaled by 1/8, exact in fp16): 128 rows x 8 uint4 chunks
    const __half2 sc = __floats2half2_rn(0.125f, 0.125f);
    for (int i = t; i < 128 * 8; i += 256) {
        int r = i >> 3, c8 = (i & 7) * 8;
        uint4 qv = *(const uint4*)&Qp[(size_t)(q0 + r) * DMODEL + c8];
        __half2* qh = (__half2*)&qv;
        qh[0] = __hmul2(qh[0], sc); qh[1] = __hmul2(qh[1], sc);
        qh[2] = __hmul2(qh[2], sc); qh[3] = __hmul2(qh[3], sc);
        *(uint4*)&Ps[r * PST2 + c8] = qv;
    }
    __syncthreads();

    uint32_t qf[4][4];
#pragma unroll
    for (int ks = 0; ks < 4; ks++) {
        int kk = ks * 16;
        qf[ks][0] = *(const uint32_t*)&Ps[qrow * PST2 + kk + 2 * tig];
        qf[ks][1] = *(const uint32_t*)&Ps[(qrow + 8) * PST2 + kk + 2 * tig];
        qf[ks][2] = *(const uint32_t*)&Ps[qrow * PST2 + kk + 2 * tig + 8];
        qf[ks][3] = *(const uint32_t*)&Ps[(qrow + 8) * PST2 + kk + 2 * tig + 8];
    }

    float oacc[8][4];
#pragma unroll
    for (int i = 0; i < 8; i++)
#pragma unroll
        for (int v = 0; v < 4; v++) oacc[i][v] = 0.f;
    float m_lo = -3.4e38f, m_hi = -3.4e38f, l_lo = 0.f, l_hi = 0.f;
    __syncthreads();

    for (int kt = 0; kt < SEQ / 64; kt++) {
        int k0 = kt << 6;
        // K rows: 64 x 8 uint4 chunks (coalesced copy)
        for (int i = t; i < 64 * 8; i += 256) {
            int r = i >> 3, c8 = (i & 7) * 8;
            *(uint4*)&Ks[r * KST2 + c8] =
                *(const uint4*)&Kp[(size_t)(k0 + r) * DMODEL + c8];
        }
        // V transposed [d][key]
        for (int i = t; i < 64 * 16; i += 256) {
            int r = i >> 4, c4 = (i & 15) * 4;
            __half2 v01 = *(const __half2*)&Vp[(size_t)(k0 + r) * DMODEL + c4];
            __half2 v23 = *(const __half2*)&Vp[(size_t)(k0 + r) * DMODEL + c4 + 2];
            Vs[(c4 + 0) * VST2 + r] = __low2half(v01);
            Vs[(c4 + 1) * VST2 + r] = __high2half(v01);
            Vs[(c4 + 2) * VST2 + r] = __low2half(v23);
            Vs[(c4 + 3) * VST2 + r] = __high2half(v23);
        }
        __syncthreads();

        // ---- S = Q @ K^T ----
        float sacc[8][4];
#pragma unroll
        for (int i = 0; i < 8; i++)
#pragma unroll
            for (int v = 0; v < 4; v++) sacc[i][v] = 0.f;
#pragma unroll
        for (int ks = 0; ks < 4; ks++) {
            int kk = ks * 16;
#pragma unroll
            for (int ni = 0; ni < 8; ni++) {
                const __half* bp = Ks + (ni * 8 + g) * KST2 + kk + 2 * tig;
                uint32_t b0 = *(const uint32_t*)(bp);
                uint32_t b1 = *(const uint32_t*)(bp + 8);
                asm volatile(
                    "mma.sync.aligned.m16n8k16.row.col.f32.f16.f16.f32 "
                    "{%0,%1,%2,%3}, {%4,%5,%6,%7}, {%8,%9}, {%0,%1,%2,%3};\n"
                    : "+f"(sacc[ni][0]), "+f"(sacc[ni][1]),
                      "+f"(sacc[ni][2]), "+f"(sacc[ni][3])
                    : "r"(qf[ks][0]), "r"(qf[ks][1]), "r"(qf[ks][2]), "r"(qf[ks][3]),
                      "r"(b0), "r"(b1));
            }
        }

        // ---- online softmax ----
        float tl = -3.4e38f, th = -3.4e38f;
#pragma unroll
        for (int ni = 0; ni < 8; ni++) {
            tl = fmaxf(tl, fmaxf(sacc[ni][0], sacc[ni][1]));
            th = fmaxf(th, fmaxf(sacc[ni][2], sacc[ni][3]));
        }
        tl = fmaxf(tl, __shfl_xor_sync(0xffffffffu, tl, 1));
        tl = fmaxf(tl, __shfl_xor_sync(0xffffffffu, tl, 2));
        th = fmaxf(th, __shfl_xor_sync(0xffffffffu, th, 1));
        th = fmaxf(th, __shfl_xor_sync(0xffffffffu, th, 2));
        float nm_lo = fmaxf(m_lo, tl), nm_hi = fmaxf(m_hi, th);
        float corr_lo = __expf(m_lo - nm_lo), corr_hi = __expf(m_hi - nm_hi);
        m_lo = nm_lo; m_hi = nm_hi;

        float sum_lo = 0.f, sum_hi = 0.f;
#pragma unroll
        for (int ni = 0; ni < 8; ni++) {
            float e0 = __expf(sacc[ni][0] - nm_lo);
            float e1 = __expf(sacc[ni][1] - nm_lo);
            float e2 = __expf(sacc[ni][2] - nm_hi);
            float e3 = __expf(sacc[ni][3] - nm_hi);
            sum_lo += e0 + e1; sum_hi += e2 + e3;
            int c = ni * 8 + 2 * tig;
            *(__half2*)&Ps[qrow * PST2 + c]       = __floats2half2_rn(e0, e1);
            *(__half2*)&Ps[(qrow + 8) * PST2 + c] = __floats2half2_rn(e2, e3);
        }
        sum_lo += __shfl_xor_sync(0xffffffffu, sum_lo, 1);
        sum_lo += __shfl_xor_sync(0xffffffffu, sum_lo, 2);
        sum_hi += __shfl_xor_sync(0xffffffffu, sum_hi, 1);
        sum_hi += __shfl_xor_sync(0xffffffffu, sum_hi, 2);
        l_lo = l_lo * corr_lo + sum_lo;
        l_hi = l_hi * corr_hi + sum_hi;

#pragma unroll
        for (int ni = 0; ni < 8; ni++) {
            oacc[ni][0] *= corr_lo; oacc[ni][1] *= corr_lo;
            oacc[ni][2] *= corr_hi; oacc[ni][3] *= corr_hi;
        }
        __syncwarp();

        // ---- O += P @ V ----
#pragma unroll
        for (int ks = 0; ks < 4; ks++) {
            int kk = ks * 16;
            uint32_t pa0 = *(const uint32_t*)&Ps[qrow * PST2 + kk + 2 * tig];
            uint32_t pa1 = *(const uint32_t*)&Ps[(qrow + 8) * PST2 + kk + 2 * tig];
            uint32_t pa2 = *(const uint32_t*)&Ps[qrow * PST2 + kk + 2 * tig + 8];
            uint32_t pa3 = *(const uint32_t*)&Ps[(qrow + 8) * PST2 + kk + 2 * tig + 8];
#pragma unroll
            for (int ni = 0; ni < 8; ni++) {
                const __half* bp = Vs + (ni * 8 + g) * VST2 + kk + 2 * tig;
                uint32_t b0 = *(const uint32_t*)(bp);
                uint32_t b1 = *(const uint32_t*)(bp + 8);
                asm volatile(
                    "mma.sync.aligned.m16n8k16.row.col.f32.f16.f16.f32 "
                    "{%0,%1,%2,%3}, {%4,%5,%6,%7}, {%8,%9}, {%0,%1,%2,%3};\n"
                    : "+f"(oacc[ni][0]), "+f"(oacc[ni][1]),
                      "+f"(oacc[ni][2]), "+f"(oacc[ni][3])
                    : "r"(pa0), "r"(pa1), "r"(pa2), "r"(pa3),
                      "r"(b0), "r"(b1));
            }
        }
        __syncthreads();
    }

    float inv_lo = 1.f / l_lo, inv_hi = 1.f / l_hi;
    __half* Op = Ob + base;
#pragma unroll
    for (int ni = 0; ni < 8; ni++) {
        int c = ni * 8 + 2 * tig;
        *(__half2*)&Op[(size_t)(q0 + qrow) * DMODEL + c] =
            __floats2half2_rn(oacc[ni][0] * inv_lo, oacc[ni][1] * inv_lo);
        *(__half2*)&Op[(size_t)(q0 + qrow + 8) * DMODEL + c] =
            __floats2half2_rn(oacc[ni][2] * inv_hi, oacc[ni][3] * inv_hi);
    }
}

// ---------------------------------------------------------------------------
// FP16 GEMM: A[M,K] fp16, Bt[N,K] fp16. 128x128x32, 2-stage, m16n8k16.
// 2 CTAs/SM via launch bounds. EPI 0: fp16 relu(acc+bias). EPI 1: fp32 +resid.
// ---------------------------------------------------------------------------
#define HAST 56
#define HSTAGE_H (2 * 128 * HAST)
#define HGEMM_SMEM (2 * HSTAGE_H * 2)

template <int EPI>
__global__ __launch_bounds__(256, 2) void hgemm(
    const __half* __restrict__ A, const __half* __restrict__ Bt,
    const float* __restrict__ bias, const float* __restrict__ resid,
    __half* __restrict__ C16, float* __restrict__ C32, int M, int N, int K)
{
    extern __shared__ __half hsm[];

    int tid = threadIdx.x;
    int wid = tid >> 5;
    int lane = tid & 31;
    int g = lane >> 2;
    int tig = lane & 3;
    int m0 = blockIdx.y * 128, n0 = blockIdx.x * 128;
    int m0w = (wid & 1) * 64;
    int n0w = (wid >> 1) * 32;

    float acc[4][4][4];
#pragma unroll
    for (int i = 0; i < 4; i++)
#pragma unroll
        for (int j = 0; j < 4; j++)
#pragma unroll
            for (int v = 0; v < 4; v++) acc[i][j][v] = 0.f;

    uint32_t smb = (uint32_t)__cvta_generic_to_shared(hsm);
#define HLOAD(K0, ST)                                                             \
    do {                                                                          \
        uint32_t sb = smb + (ST) * HSTAGE_H * 2;                                  \
        _Pragma("unroll")                                                         \
        for (int j = 0; j < 4; j++) {                                             \
            int c = tid + j * 256;                                                \
            int tile = c >> 9, cc = c & 511, row = cc >> 2, q = cc & 3;           \
            const __half* gp = tile ? (Bt + (size_t)(n0 + row) * K + (K0) + q * 8)\
                                    : (A + (size_t)(m0 + row) * K + (K0) + q * 8);\
            uint32_t sp = sb + (uint32_t)(tile * 128 * HAST + row * HAST + q * 8) * 2; \
            asm volatile("cp.async.ca.shared.global [%0], [%1], 16;\n" ::         \
                "r"(sp), "l"(gp));                                                \
        }                                                                         \
    } while (0)

    int KT = K >> 5;
    HLOAD(0, 0);
    asm volatile("cp.async.commit_group;\n");

    for (int kt = 0; kt < KT; kt++) {
        if (kt + 1 < KT) {
            HLOAD((kt + 1) << 5, (kt + 1) & 1);
            asm volatile("cp.async.commit_group;\n");
            asm volatile("cp.async.wait_group 1;\n");
        } else {
            asm volatile("cp.async.wait_group 0;\n");
        }
        __syncthreads();
        const __half* as = hsm + (kt & 1) * HSTAGE_H;
        const __half* bs = as + 128 * HAST;
#pragma unroll
        for (int ks = 0; ks < 2; ks++) {
            int kk = ks * 16;
            uint32_t af[4][4], bf[4][2];
#pragma unroll
            for (int mi = 0; mi < 4; mi++) {
                const __half* ap = as + (m0w + mi * 16 + g) * HAST + kk + 2 * tig;
                af[mi][0] = *(const uint32_t*)(ap);
                af[mi][1] = *(const uint32_t*)(ap + 8 * HAST);
                af[mi][2] = *(const uint32_t*)(ap + 8);
                af[mi][3] = *(const uint32_t*)(ap + 8 * HAST + 8);
            }
#pragma unroll
            for (int ni = 0; ni < 4; ni++) {
                const __half* bp = bs + (n0w + ni * 8 + g) * HAST + kk + 2 * tig;
                bf[ni][0] = *(const uint32_t*)(bp);
                bf[ni][1] = *(const uint32_t*)(bp + 8);
            }
#pragma unroll
            for (int mi = 0; mi < 4; mi++)
#pragma unroll
                for (int ni = 0; ni < 4; ni++) {
                    asm volatile(
                        "mma.sync.aligned.m16n8k16.row.col.f32.f16.f16.f32 "
                        "{%0,%1,%2,%3}, {%4,%5,%6,%7}, {%8,%9}, {%0,%1,%2,%3};\n"
                        : "+f"(acc[mi][ni][0]), "+f"(acc[mi][ni][1]),
                          "+f"(acc[mi][ni][2]), "+f"(acc[mi][ni][3])
                        : "r"(af[mi][0]), "r"(af[mi][1]), "r"(af[mi][2]), "r"(af[mi][3]),
                          "r"(bf[ni][0]), "r"(bf[ni][1]));
                }
        }
        __syncthreads();
    }

#pragma unroll
    for (int mi = 0; mi < 4; mi++) {
        int r0 = m0 + m0w + mi * 16 + g;
#pragma unroll
        for (int ni = 0; ni < 4; ni++) {
            int c = n0 + n0w + ni * 8 + 2 * tig;
            float b0 = bias[c], b1 = bias[c + 1];
            float v0 = acc[mi][ni][0] + b0;
            float v1 = acc[mi][ni][1] + b1;
            float v2 = acc[mi][ni][2] + b0;
            float v3 = acc[mi][ni][3] + b1;
            if (EPI == 0) {
                v0 = fmaxf(v0, 0.f); v1 = fmaxf(v1, 0.f);
                v2 = fmaxf(v2, 0.f); v3 = fmaxf(v3, 0.f);
                *(__half2*)&C16[(size_t)r0 * N + c] = __floats2half2_rn(v0, v1);
                *(__half2*)&C16[(size_t)(r0 + 8) * N + c] = __floats2half2_rn(v2, v3);
            } else {
                v0 += resid[(size_t)r0 * N + c];
                v1 += resid[(size_t)r0 * N + c + 1];
                v2 += resid[(size_t)(r0 + 8) * N + c];
                v3 += resid[(size_t)(r0 + 8) * N + c + 1];
                *(float2*)&C32[(size_t)r0 * N + c] = make_float2(v0, v1);
                *(float2*)&C32[(size_t)(r0 + 8) * N + c] = make_float2(v2, v3);
            }
        }
    }
#undef HLOAD
}

// ---------------------------------------------------------------------------
extern "C" void kernel_launch(void* const* d_in, const int* in_sizes, int n_in,
                              void* d_out, int out_size)
{
    const float* tgt    = (const float*)d_in[0];
    const float* memory = (const float*)d_in[1];
    const float* sa_w   = (const float*)d_in[4];
    const float* sa_b   = (const float*)d_in[5];
    const float* mha_w  = (const float*)d_in[6];
    const float* mha_b  = (const float*)d_in[7];
    const float* ff_w1  = (const float*)d_in[8];
    const float* ff_b1  = (const float*)d_in[9];
    const float* ff_w2  = (const float*)d_in[10];
    const float* ff_b2  = (const float*)d_in[11];
    const float* ln1g   = (const float*)d_in[12];
    const float* ln1b   = (const float*)d_in[13];
    const float* ln2g   = (const float*)d_in[14];
    const float* ln2b   = (const float*)d_in[15];
    const float* ln3g   = (const float*)d_in[16];
    const float* ln3b   = (const float*)d_in[17];
    float* out = (float*)d_out;

    float *x1;
    __half *attn16, *h16, *mem16, *mid16, *wsat, *wmhat, *w1t, *w2t;
    cudaGetSymbolAddress((void**)&x1,     g_x1);
    cudaGetSymbolAddress((void**)&attn16, g_attn16);
    cudaGetSymbolAddress((void**)&h16,    g_h16);
    cudaGetSymbolAddress((void**)&mem16,  g_mem16);
    cudaGetSymbolAddress((void**)&mid16,  g_mid16);
    cudaGetSymbolAddress((void**)&wsat,   g_wsat);
    cudaGetSymbolAddress((void**)&wmhat,  g_wmhat);
    cudaGetSymbolAddress((void**)&w1t,    g_w1t);
    cudaGetSymbolAddress((void**)&w2t,    g_w2t);

    cudaFuncSetAttribute(attn_h, cudaFuncAttributeMaxDynamicSharedMemorySize, ATTN_SMEM);
    cudaFuncSetAttribute(hgemm<0>, cudaFuncAttributeMaxDynamicSharedMemorySize, HGEMM_SMEM);
    cudaFuncSetAttribute(hgemm<1>, cudaFuncAttributeMaxDynamicSharedMemorySize, HGEMM_SMEM);

    dim3 attn_grid(BATCH * NHEAD, SEQ / 128);
    dim3 gfc(DMODEL / 128, MROWS / 128);     // (8, 32)
    dim3 gff1(DFF / 128, MROWS / 128);       // (32, 32)

    // prep: weights (transpose+cvt) + memory (cvt)
    wcvt_kernel<<<dim3(DMODEL / 32, DMODEL / 32), 256>>>(sa_w, wsat, DMODEL, DMODEL);
    wcvt_kernel<<<dim3(DMODEL / 32, DMODEL / 32), 256>>>(mha_w, wmhat, DMODEL, DMODEL);
    wcvt_kernel<<<dim3(DFF / 32, DMODEL / 32), 256>>>(ff_w1, w1t, DMODEL, DFF);
    wcvt_kernel<<<dim3(DMODEL / 32, DFF / 32), 256>>>(ff_w2, w2t, DFF, DMODEL);
    cvt16_kernel<<<MROWS * DMODEL / 4 / 256, 256>>>(memory, mem16, MROWS * DMODEL / 4);

    // ---- self-attention block ----
    ln_kernel<<<MROWS, 256>>>(tgt, ln1g, ln1b, h16);
    attn_h<<<attn_grid, 256, ATTN_SMEM>>>(h16, h16, h16, attn16);
    hgemm<1><<<gfc, 256, HGEMM_SMEM>>>(attn16, wsat, sa_b, tgt,
                                       nullptr, x1, MROWS, DMODEL, DMODEL);
    // ---- cross-attention block (Q=K=memory, V=LN2(x)) ----
    ln_kernel<<<MROWS, 256>>>(x1, ln2g, ln2b, h16);
    attn_h<<<attn_grid, 256, ATTN_SMEM>>>(mem16, mem16, h16, attn16);
    hgemm<1><<<gfc, 256, HGEMM_SMEM>>>(attn16, wmhat, mha_b, x1,
                                       nullptr, out, MROWS, DMODEL, DMODEL);
    // ---- FFN block ----
    ln_kernel<<<MROWS, 256>>>(out, ln3g, ln3b, h16);
    hgemm<0><<<gff1, 256, HGEMM_SMEM>>>(h16, w1t, ff_b1, nullptr,
                                        mid16, nullptr, MROWS, DFF, DMODEL);
    hgemm<1><<<gfc, 256, HGEMM_SMEM>>>(mid16, w2t, ff_b2, out,
                                       nullptr, out, MROWS, DMODEL, DFF);
}

// round 11
// speedup vs baseline: 1.8019x; 1.0791x over previous
#include <cuda_runtime.h>
#include <cuda_fp16.h>
#include <math.h>
#include <stdint.h>

#define BATCH 4
#define SEQ 1024
#define DMODEL 1024
#define NHEAD 16
#define DHEAD 64
#define DFF 4096
#define MROWS (BATCH * SEQ)

__device__ float g_x1[MROWS * DMODEL];         // residual stream
__device__ __half g_attn16[MROWS * DMODEL];    // attention out (fp16)
__device__ __half g_h16[MROWS * DMODEL];       // LN out (fp16)
__device__ __half g_mem16[MROWS * DMODEL];     // memory (fp16)
__device__ __half g_mid16[MROWS * DFF];        // FFN hidden (fp16)
__device__ __half g_wsat[DMODEL * DMODEL];     // sa_w^T fp16
__device__ __half g_wmhat[DMODEL * DMODEL];    // mha_w^T fp16
__device__ __half g_w1t[DFF * DMODEL];         // ff_w1^T fp16
__device__ __half g_w2t[DMODEL * DFF];         // ff_w2^T fp16

#define LDSM4(r0, r1, r2, r3, addr)                                        \
    asm volatile("ldmatrix.sync.aligned.m8n8.x4.shared.b16 "               \
                 "{%0,%1,%2,%3}, [%4];"                                    \
                 : "=r"(r0), "=r"(r1), "=r"(r2), "=r"(r3) : "r"(addr))

#define MMA16816(d, a0, a1, a2, a3, b0, b1)                                \
    asm volatile("mma.sync.aligned.m16n8k16.row.col.f32.f16.f16.f32 "      \
                 "{%0,%1,%2,%3}, {%4,%5,%6,%7}, {%8,%9}, {%0,%1,%2,%3};\n" \
                 : "+f"(d[0]), "+f"(d[1]), "+f"(d[2]), "+f"(d[3])          \
                 : "r"(a0), "r"(a1), "r"(a2), "r"(a3), "r"(b0), "r"(b1))

// ---------------------------------------------------------------------------
// fp32 -> fp16 convert
// ---------------------------------------------------------------------------
__global__ __launch_bounds__(256) void cvt16_kernel(
    const float* __restrict__ in, __half* __restrict__ out, int n4)
{
    int i = blockIdx.x * 256 + threadIdx.x;
    if (i < n4) {
        float4 v = ((const float4*)in)[i];
        ((__half2*)out)[2 * i]     = __floats2half2_rn(v.x, v.y);
        ((__half2*)out)[2 * i + 1] = __floats2half2_rn(v.z, v.w);
    }
}

// ---------------------------------------------------------------------------
// LayerNorm -> fp16
// ---------------------------------------------------------------------------
__global__ __launch_bounds__(256) void ln_kernel(
    const float* __restrict__ x, const float* __restrict__ gam,
    const float* __restrict__ bet, __half* __restrict__ out16)
{
    int row = blockIdx.x;
    const float* xr = x + (size_t)row * DMODEL;
    float v[4];
    float s = 0.f, s2 = 0.f;
#pragma unroll
    for (int i = 0; i < 4; i++) {
        v[i] = xr[threadIdx.x + i * 256];
        s += v[i];
        s2 += v[i] * v[i];
    }
#pragma unroll
    for (int o = 16; o; o >>= 1) {
        s  += __shfl_xor_sync(0xffffffffu, s, o);
        s2 += __shfl_xor_sync(0xffffffffu, s2, o);
    }
    __shared__ float red[2][8];
    int w = threadIdx.x >> 5, l = threadIdx.x & 31;
    if (l == 0) { red[0][w] = s; red[1][w] = s2; }
    __syncthreads();
    s = 0.f; s2 = 0.f;
#pragma unroll
    for (int i = 0; i < 8; i++) { s += red[0][i]; s2 += red[1][i]; }
    float mean = s * (1.0f / DMODEL);
    float var  = s2 * (1.0f / DMODEL) - mean * mean;
    float rstd = rsqrtf(var + 1e-5f);
#pragma unroll
    for (int i = 0; i < 4; i++) {
        int c = threadIdx.x + i * 256;
        float y = (v[i] - mean) * rstd * gam[c] + bet[c];
        out16[(size_t)row * DMODEL + c] = __float2half_rn(y);
    }
}

// ---------------------------------------------------------------------------
// Weight transpose+convert: W[K,N] fp32 -> Wt[N,K] fp16
// ---------------------------------------------------------------------------
__global__ __launch_bounds__(256) void wcvt_kernel(
    const float* __restrict__ W, __half* __restrict__ Wt, int K, int N)
{
    __shared__ float tile[32][33];
    int k0 = blockIdx.y * 32, n0 = blockIdx.x * 32;
    int tx = threadIdx.x & 31, ty = threadIdx.x >> 5;
#pragma unroll
    for (int j = 0; j < 4; j++)
        tile[ty + 8 * j][tx] = W[(size_t)(k0 + ty + 8 * j) * N + n0 + tx];
    __syncthreads();
#pragma unroll
    for (int j = 0; j < 4; j++) {
        int n = n0 + ty + 8 * j, k = k0 + tx;
        Wt[(size_t)n * K + k] = __float2half_rn(tile[tx][ty + 8 * j]);
    }
}

// ---------------------------------------------------------------------------
// FP16 flash attention with ldmatrix fragment loads.
// ---------------------------------------------------------------------------
#define PST2 72
#define KST2 72
#define VST2 72
#define ATTN_SMEM ((128 * PST2 + 64 * KST2 + 64 * VST2) * 2)

__global__ __launch_bounds__(256) void attn_h(
    const __half* __restrict__ Qb, const __half* __restrict__ Kb,
    const __half* __restrict__ Vb, __half* __restrict__ Ob)
{
    extern __shared__ __half hsm[];
    __half* Ps = hsm;
    __half* Ks = Ps + 128 * PST2;
    __half* Vs = Ks + 64 * KST2;

    int bh = blockIdx.x;
    int b = bh >> 4, h = bh & 15;
    int q0 = blockIdx.y << 7;
    int t = threadIdx.x, w = t >> 5, lane = t & 31;
    int g = lane >> 2, tig = lane & 3;
    int qrow = w * 16 + g;

    size_t base = ((size_t)b * SEQ) * DMODEL + (size_t)h * DHEAD;
    const __half* Qp = Qb + base;
    const __half* Kp = Kb + base;
    const __half* Vp = Vb + base;

    uint32_t ps_b = (uint32_t)__cvta_generic_to_shared(Ps);
    uint32_t ks_b = (uint32_t)__cvta_generic_to_shared(Ks);
    uint32_t vs_b = (uint32_t)__cvta_generic_to_shared(Vs);

    // ldmatrix per-lane addresses
    int m4 = lane >> 3;           // matrix index 0..3
    // A-type (Q/P): rows w*16 + (lane&15), col (lane>>4)*8
    uint32_t paddr = ps_b + (uint32_t)((w * 16 + (lane & 15)) * PST2 + (lane >> 4) * 8) * 2;
    // B-type pairs (K/V): pair p covers ni=2p,2p+1; lane -> ni_off=(m4>>1), col=(m4&1)*8
    uint32_t kaddr[4], vaddr[4];
#pragma unroll
    for (int p = 0; p < 4; p++) {
        int row = (2 * p + (m4 >> 1)) * 8 + (lane & 7);
        int col = (m4 & 1) * 8;
        kaddr[p] = ks_b + (uint32_t)(row * KST2 + col) * 2;
        vaddr[p] = vs_b + (uint32_t)(row * VST2 + col) * 2;
    }

    // Stage Q (scaled by 1/8, exact)
    const __half2 sc = __floats2half2_rn(0.125f, 0.125f);
    for (int i = t; i < 128 * 8; i += 256) {
        int r = i >> 3, c8 = (i & 7) * 8;
        uint4 qv = *(const uint4*)&Qp[(size_t)(q0 + r) * DMODEL + c8];
        __half2* qh = (__half2*)&qv;
        qh[0] = __hmul2(qh[0], sc); qh[1] = __hmul2(qh[1], sc);
        qh[2] = __hmul2(qh[2], sc); qh[3] = __hmul2(qh[3], sc);
        *(uint4*)&Ps[r * PST2 + c8] = qv;
    }
    __syncthreads();

    uint32_t qf[4][4];
#pragma unroll
    for (int ks = 0; ks < 4; ks++)
        LDSM4(qf[ks][0], qf[ks][1], qf[ks][2], qf[ks][3], paddr + ks * 32);

    float oacc[8][4];
#pragma unroll
    for (int i = 0; i < 8; i++)
#pragma unroll
        for (int v = 0; v < 4; v++) oacc[i][v] = 0.f;
    float m_lo = -3.4e38f, m_hi = -3.4e38f, l_lo = 0.f, l_hi = 0.f;
    __syncthreads();

    for (int kt = 0; kt < SEQ / 64; kt++) {
        int k0 = kt << 6;
        for (int i = t; i < 64 * 8; i += 256) {
            int r = i >> 3, c8 = (i & 7) * 8;
            *(uint4*)&Ks[r * KST2 + c8] =
                *(const uint4*)&Kp[(size_t)(k0 + r) * DMODEL + c8];
        }
        for (int i = t; i < 64 * 16; i += 256) {
            int r = i >> 4, c4 = (i & 15) * 4;
            __half2 v01 = *(const __half2*)&Vp[(size_t)(k0 + r) * DMODEL + c4];
            __half2 v23 = *(const __half2*)&Vp[(size_t)(k0 + r) * DMODEL + c4 + 2];
            Vs[(c4 + 0) * VST2 + r] = __low2half(v01);
            Vs[(c4 + 1) * VST2 + r] = __high2half(v01);
            Vs[(c4 + 2) * VST2 + r] = __low2half(v23);
            Vs[(c4 + 3) * VST2 + r] = __high2half(v23);
        }
        __syncthreads();

        // ---- S = Q @ K^T ----
        float sacc[8][4];
#pragma unroll
        for (int i = 0; i < 8; i++)
#pragma unroll
            for (int v = 0; v < 4; v++) sacc[i][v] = 0.f;
#pragma unroll
        for (int ks = 0; ks < 4; ks++) {
#pragma unroll
            for (int p = 0; p < 4; p++) {
                uint32_t b0, b1, b2, b3;
                LDSM4(b0, b1, b2, b3, kaddr[p] + ks * 32);
                MMA16816(sacc[2 * p],     qf[ks][0], qf[ks][1], qf[ks][2], qf[ks][3], b0, b1);
                MMA16816(sacc[2 * p + 1], qf[ks][0], qf[ks][1], qf[ks][2], qf[ks][3], b2, b3);
            }
        }

        // ---- online softmax ----
        float tl = -3.4e38f, th = -3.4e38f;
#pragma unroll
        for (int ni = 0; ni < 8; ni++) {
            tl = fmaxf(tl, fmaxf(sacc[ni][0], sacc[ni][1]));
            th = fmaxf(th, fmaxf(sacc[ni][2], sacc[ni][3]));
        }
        tl = fmaxf(tl, __shfl_xor_sync(0xffffffffu, tl, 1));
        tl = fmaxf(tl, __shfl_xor_sync(0xffffffffu, tl, 2));
        th = fmaxf(th, __shfl_xor_sync(0xffffffffu, th, 1));
        th = fmaxf(th, __shfl_xor_sync(0xffffffffu, th, 2));
        float nm_lo = fmaxf(m_lo, tl), nm_hi = fmaxf(m_hi, th);
        float corr_lo = __expf(m_lo - nm_lo), corr_hi = __expf(m_hi - nm_hi);
        m_lo = nm_lo; m_hi = nm_hi;

        float sum_lo = 0.f, sum_hi = 0.f;
#pragma unroll
        for (int ni = 0; ni < 8; ni++) {
            float e0 = __expf(sacc[ni][0] - nm_lo);
            float e1 = __expf(sacc[ni][1] - nm_lo);
            float e2 = __expf(sacc[ni][2] - nm_hi);
            float e3 = __expf(sacc[ni][3] - nm_hi);
            sum_lo += e0 + e1; sum_hi += e2 + e3;
            int c = ni * 8 + 2 * tig;
            *(__half2*)&Ps[qrow * PST2 + c]       = __floats2half2_rn(e0, e1);
            *(__half2*)&Ps[(qrow + 8) * PST2 + c] = __floats2half2_rn(e2, e3);
        }
        sum_lo += __shfl_xor_sync(0xffffffffu, sum_lo, 1);
        sum_lo += __shfl_xor_sync(0xffffffffu, sum_lo, 2);
        sum_hi += __shfl_xor_sync(0xffffffffu, sum_hi, 1);
        sum_hi += __shfl_xor_sync(0xffffffffu, sum_hi, 2);
        l_lo = l_lo * corr_lo + sum_lo;
        l_hi = l_hi * corr_hi + sum_hi;

#pragma unroll
        for (int ni = 0; ni < 8; ni++) {
            oacc[ni][0] *= corr_lo; oacc[ni][1] *= corr_lo;
            oacc[ni][2] *= corr_hi; oacc[ni][3] *= corr_hi;
        }
        __syncwarp();

        // ---- O += P @ V ----
#pragma unroll
        for (int ks = 0; ks < 4; ks++) {
            uint32_t pa0, pa1, pa2, pa3;
            LDSM4(pa0, pa1, pa2, pa3, paddr + ks * 32);
#pragma unroll
            for (int p = 0; p < 4; p++) {
                uint32_t b0, b1, b2, b3;
                LDSM4(b0, b1, b2, b3, vaddr[p] + ks * 32);
                MMA16816(oacc[2 * p],     pa0, pa1, pa2, pa3, b0, b1);
                MMA16816(oacc[2 * p + 1], pa0, pa1, pa2, pa3, b2, b3);
            }
        }
        __syncthreads();
    }

    float inv_lo = 1.f / l_lo, inv_hi = 1.f / l_hi;
    __half* Op = Ob + base;
#pragma unroll
    for (int ni = 0; ni < 8; ni++) {
        int c = ni * 8 + 2 * tig;
        *(__half2*)&Op[(size_t)(q0 + qrow) * DMODEL + c] =
            __floats2half2_rn(oacc[ni][0] * inv_lo, oacc[ni][1] * inv_lo);
        *(__half2*)&Op[(size_t)(q0 + qrow + 8) * DMODEL + c] =
            __floats2half2_rn(oacc[ni][2] * inv_hi, oacc[ni][3] * inv_hi);
    }
}

// ---------------------------------------------------------------------------
// FP16 GEMM with ldmatrix fragment loads. 128x128x32, 2-stage, m16n8k16.
// ---------------------------------------------------------------------------
#define HAST 56
#define HSTAGE_H (2 * 128 * HAST)
#define HGEMM_SMEM (2 * HSTAGE_H * 2)

template <int EPI>
__global__ __launch_bounds__(256, 2) void hgemm(
    const __half* __restrict__ A, const __half* __restrict__ Bt,
    const float* __restrict__ bias, const float* __restrict__ resid,
    __half* __restrict__ C16, float* __restrict__ C32, int M, int N, int K)
{
    extern __shared__ __half hsm[];

    int tid = threadIdx.x;
    int wid = tid >> 5;
    int lane = tid & 31;
    int g = lane >> 2;
    int tig = lane & 3;
    int m0 = blockIdx.y * 128, n0 = blockIdx.x * 128;
    int m0w = (wid & 1) * 64;
    int n0w = (wid >> 1) * 32;
    int m4 = lane >> 3;

    float acc[4][4][4];
#pragma unroll
    for (int i = 0; i < 4; i++)
#pragma unroll
        for (int j = 0; j < 4; j++)
#pragma unroll
            for (int v = 0; v < 4; v++) acc[i][j][v] = 0.f;

    uint32_t smb = (uint32_t)__cvta_generic_to_shared(hsm);

    // ldmatrix addresses (stage-0 base; add stage offset + kk*2 at use)
    uint32_t aaddr[4], baddr[2];
#pragma unroll
    for (int mi = 0; mi < 4; mi++)
        aaddr[mi] = smb + (uint32_t)((m0w + mi * 16 + (lane & 15)) * HAST
                                     + (lane >> 4) * 8) * 2;
#pragma unroll
    for (int p = 0; p < 2; p++) {
        int row = n0w + (2 * p + (m4 >> 1)) * 8 + (lane & 7);
        int col = (m4 & 1) * 8;
        baddr[p] = smb + (uint32_t)(128 * HAST + row * HAST + col) * 2;
    }

#define HLOAD(K0, ST)                                                             \
    do {                                                                          \
        uint32_t sb = smb + (ST) * HSTAGE_H * 2;                                  \
        _Pragma("unroll")                                                         \
        for (int j = 0; j < 4; j++) {                                             \
            int c = tid + j * 256;                                                \
            int tile = c >> 9, cc = c & 511, row = cc >> 2, q = cc & 3;           \
            const __half* gp = tile ? (Bt + (size_t)(n0 + row) * K + (K0) + q * 8)\
                                    : (A + (size_t)(m0 + row) * K + (K0) + q * 8);\
            uint32_t sp = sb + (uint32_t)(tile * 128 * HAST + row * HAST + q * 8) * 2; \
            asm volatile("cp.async.ca.shared.global [%0], [%1], 16;\n" ::         \
                "r"(sp), "l"(gp));                                                \
        }                                                                         \
    } while (0)

    int KT = K >> 5;
    HLOAD(0, 0);
    asm volatile("cp.async.commit_group;\n");

    for (int kt = 0; kt < KT; kt++) {
        if (kt + 1 < KT) {
            HLOAD((kt + 1) << 5, (kt + 1) & 1);
            asm volatile("cp.async.commit_group;\n");
            asm volatile("cp.async.wait_group 1;\n");
        } else {
            asm volatile("cp.async.wait_group 0;\n");
        }
        __syncthreads();
        uint32_t stoff = (uint32_t)(kt & 1) * HSTAGE_H * 2;
#pragma unroll
        for (int ks = 0; ks < 2; ks++) {
            uint32_t ko = stoff + ks * 32;   // kk*2 bytes (kk = ks*16)
            uint32_t af[4][4], bf[4][2];
#pragma unroll
            for (int mi = 0; mi < 4; mi++)
                LDSM4(af[mi][0], af[mi][1], af[mi][2], af[mi][3], aaddr[mi] + ko);
#pragma unroll
            for (int p = 0; p < 2; p++)
                LDSM4(bf[2 * p][0], bf[2 * p][1], bf[2 * p + 1][0], bf[2 * p + 1][1],
                      baddr[p] + ko);
#pragma unroll
            for (int mi = 0; mi < 4; mi++)
#pragma unroll
                for (int ni = 0; ni < 4; ni++)
                    MMA16816(acc[mi][ni], af[mi][0], af[mi][1], af[mi][2], af[mi][3],
                             bf[ni][0], bf[ni][1]);
        }
        __syncthreads();
    }

#pragma unroll
    for (int mi = 0; mi < 4; mi++) {
        int r0 = m0 + m0w + mi * 16 + g;
#pragma unroll
        for (int ni = 0; ni < 4; ni++) {
            int c = n0 + n0w + ni * 8 + 2 * tig;
            float b0 = bias[c], b1 = bias[c + 1];
            float v0 = acc[mi][ni][0] + b0;
            float v1 = acc[mi][ni][1] + b1;
            float v2 = acc[mi][ni][2] + b0;
            float v3 = acc[mi][ni][3] + b1;
            if (EPI == 0) {
                v0 = fmaxf(v0, 0.f); v1 = fmaxf(v1, 0.f);
                v2 = fmaxf(v2, 0.f); v3 = fmaxf(v3, 0.f);
                *(__half2*)&C16[(size_t)r0 * N + c] = __floats2half2_rn(v0, v1);
                *(__half2*)&C16[(size_t)(r0 + 8) * N + c] = __floats2half2_rn(v2, v3);
            } else {
                v0 += resid[(size_t)r0 * N + c];
                v1 += resid[(size_t)r0 * N + c + 1];
                v2 += resid[(size_t)(r0 + 8) * N + c];
                v3 += resid[(size_t)(r0 + 8) * N + c + 1];
                *(float2*)&C32[(size_t)r0 * N + c] = make_float2(v0, v1);
                *(float2*)&C32[(size_t)(r0 + 8) * N + c] = make_float2(v2, v3);
            }
        }
    }
#undef HLOAD
}

// ---------------------------------------------------------------------------
extern "C" void kernel_launch(void* const* d_in, const int* in_sizes, int n_in,
                              void* d_out, int out_size)
{
    const float* tgt    = (const float*)d_in[0];
    const float* memory = (const float*)d_in[1];
    const float* sa_w   = (const float*)d_in[4];
    const float* sa_b   = (const float*)d_in[5];
    const float* mha_w  = (const float*)d_in[6];
    const float* mha_b  = (const float*)d_in[7];
    const float* ff_w1  = (const float*)d_in[8];
    const float* ff_b1  = (const float*)d_in[9];
    const float* ff_w2  = (const float*)d_in[10];
    const float* ff_b2  = (const float*)d_in[11];
    const float* ln1g   = (const float*)d_in[12];
    const float* ln1b   = (const float*)d_in[13];
    const float* ln2g   = (const float*)d_in[14];
    const float* ln2b   = (const float*)d_in[15];
    const float* ln3g   = (const float*)d_in[16];
    const float* ln3b   = (const float*)d_in[17];
    float* out = (float*)d_out;

    float *x1;
    __half *attn16, *h16, *mem16, *mid16, *wsat, *wmhat, *w1t, *w2t;
    cudaGetSymbolAddress((void**)&x1,     g_x1);
    cudaGetSymbolAddress((void**)&attn16, g_attn16);
    cudaGetSymbolAddress((void**)&h16,    g_h16);
    cudaGetSymbolAddress((void**)&mem16,  g_mem16);
    cudaGetSymbolAddress((void**)&mid16,  g_mid16);
    cudaGetSymbolAddress((void**)&wsat,   g_wsat);
    cudaGetSymbolAddress((void**)&wmhat,  g_wmhat);
    cudaGetSymbolAddress((void**)&w1t,    g_w1t);
    cudaGetSymbolAddress((void**)&w2t,    g_w2t);

    cudaFuncSetAttribute(attn_h, cudaFuncAttributeMaxDynamicSharedMemorySize, ATTN_SMEM);
    cudaFuncSetAttribute(hgemm<0>, cudaFuncAttributeMaxDynamicSharedMemorySize, HGEMM_SMEM);
    cudaFuncSetAttribute(hgemm<1>, cudaFuncAttributeMaxDynamicSharedMemorySize, HGEMM_SMEM);

    dim3 attn_grid(BATCH * NHEAD, SEQ / 128);
    dim3 gfc(DMODEL / 128, MROWS / 128);     // (8, 32)
    dim3 gff1(DFF / 128, MROWS / 128);       // (32, 32)

    // prep
    wcvt_kernel<<<dim3(DMODEL / 32, DMODEL / 32), 256>>>(sa_w, wsat, DMODEL, DMODEL);
    wcvt_kernel<<<dim3(DMODEL / 32, DMODEL / 32), 256>>>(mha_w, wmhat, DMODEL, DMODEL);
    wcvt_kernel<<<dim3(DFF / 32, DMODEL / 32), 256>>>(ff_w1, w1t, DMODEL, DFF);
    wcvt_kernel<<<dim3(DMODEL / 32, DFF / 32), 256>>>(ff_w2, w2t, DFF, DMODEL);
    cvt16_kernel<<<MROWS * DMODEL / 4 / 256, 256>>>(memory, mem16, MROWS * DMODEL / 4);

    // ---- self-attention block ----
    ln_kernel<<<MROWS, 256>>>(tgt, ln1g, ln1b, h16);
    attn_h<<<attn_grid, 256, ATTN_SMEM>>>(h16, h16, h16, attn16);
    hgemm<1><<<gfc, 256, HGEMM_SMEM>>>(attn16, wsat, sa_b, tgt,
                                       nullptr, x1, MROWS, DMODEL, DMODEL);
    // ---- cross-attention block (Q=K=memory, V=LN2(x)) ----
    ln_kernel<<<MROWS, 256>>>(x1, ln2g, ln2b, h16);
    attn_h<<<attn_grid, 256, ATTN_SMEM>>>(mem16, mem16, h16, attn16);
    hgemm<1><<<gfc, 256, HGEMM_SMEM>>>(attn16, wmhat, mha_b, x1,
                                       nullptr, out, MROWS, DMODEL, DMODEL);
    // ---- FFN block ----
    ln_kernel<<<MROWS, 256>>>(out, ln3g, ln3b, h16);
    hgemm<0><<<gff1, 256, HGEMM_SMEM>>>(h16, w1t, ff_b1, nullptr,
                                        mid16, nullptr, MROWS, DFF, DMODEL);
    hgemm<1><<<gfc, 256, HGEMM_SMEM>>>(mid16, w2t, ff_b2, out,
                                       nullptr, out, MROWS, DMODEL, DFF);
}

// round 12
// speedup vs baseline: 2.0260x; 1.1244x over previous
#include <cuda_runtime.h>
#include <cuda_fp16.h>
#include <math.h>
#include <stdint.h>

#define BATCH 4
#define SEQ 1024
#define DMODEL 1024
#define NHEAD 16
#define DHEAD 64
#define DFF 4096
#define MROWS (BATCH * SEQ)

__device__ float g_x1[MROWS * DMODEL];         // residual stream
__device__ __half g_attn16[MROWS * DMODEL];    // attention out (fp16)
__device__ __half g_h16[MROWS * DMODEL];       // LN out (fp16)
__device__ __half g_mem16[MROWS * DMODEL];     // memory (fp16)
__device__ __half g_mid16[MROWS * DFF];        // FFN hidden (fp16)
__device__ __half g_wsat[DMODEL * DMODEL];     // sa_w^T fp16
__device__ __half g_wmhat[DMODEL * DMODEL];    // mha_w^T fp16
__device__ __half g_w1t[DFF * DMODEL];         // ff_w1^T fp16
__device__ __half g_w2t[DMODEL * DFF];         // ff_w2^T fp16

#define LDSM4(r0, r1, r2, r3, addr)                                        \
    asm volatile("ldmatrix.sync.aligned.m8n8.x4.shared.b16 "               \
                 "{%0,%1,%2,%3}, [%4];"                                    \
                 : "=r"(r0), "=r"(r1), "=r"(r2), "=r"(r3) : "r"(addr))

#define MMA16816(d, a0, a1, a2, a3, b0, b1)                                \
    asm volatile("mma.sync.aligned.m16n8k16.row.col.f32.f16.f16.f32 "      \
                 "{%0,%1,%2,%3}, {%4,%5,%6,%7}, {%8,%9}, {%0,%1,%2,%3};\n" \
                 : "+f"(d[0]), "+f"(d[1]), "+f"(d[2]), "+f"(d[3])          \
                 : "r"(a0), "r"(a1), "r"(a2), "r"(a3), "r"(b0), "r"(b1))

// ---------------------------------------------------------------------------
// fp32 -> fp16 convert
// ---------------------------------------------------------------------------
__global__ __launch_bounds__(256) void cvt16_kernel(
    const float* __restrict__ in, __half* __restrict__ out, int n4)
{
    int i = blockIdx.x * 256 + threadIdx.x;
    if (i < n4) {
        float4 v = ((const float4*)in)[i];
        ((__half2*)out)[2 * i]     = __floats2half2_rn(v.x, v.y);
        ((__half2*)out)[2 * i + 1] = __floats2half2_rn(v.z, v.w);
    }
}

// ---------------------------------------------------------------------------
// LayerNorm -> fp16
// ---------------------------------------------------------------------------
__global__ __launch_bounds__(256) void ln_kernel(
    const float* __restrict__ x, const float* __restrict__ gam,
    const float* __restrict__ bet, __half* __restrict__ out16)
{
    int row = blockIdx.x;
    const float* xr = x + (size_t)row * DMODEL;
    float v[4];
    float s = 0.f, s2 = 0.f;
#pragma unroll
    for (int i = 0; i < 4; i++) {
        v[i] = xr[threadIdx.x + i * 256];
        s += v[i];
        s2 += v[i] * v[i];
    }
#pragma unroll
    for (int o = 16; o; o >>= 1) {
        s  += __shfl_xor_sync(0xffffffffu, s, o);
        s2 += __shfl_xor_sync(0xffffffffu, s2, o);
    }
    __shared__ float red[2][8];
    int w = threadIdx.x >> 5, l = threadIdx.x & 31;
    if (l == 0) { red[0][w] = s; red[1][w] = s2; }
    __syncthreads();
    s = 0.f; s2 = 0.f;
#pragma unroll
    for (int i = 0; i < 8; i++) { s += red[0][i]; s2 += red[1][i]; }
    float mean = s * (1.0f / DMODEL);
    float var  = s2 * (1.0f / DMODEL) - mean * mean;
    float rstd = rsqrtf(var + 1e-5f);
#pragma unroll
    for (int i = 0; i < 4; i++) {
        int c = threadIdx.x + i * 256;
        float y = (v[i] - mean) * rstd * gam[c] + bet[c];
        out16[(size_t)row * DMODEL + c] = __float2half_rn(y);
    }
}

// ---------------------------------------------------------------------------
// Weight transpose+convert: W[K,N] fp32 -> Wt[N,K] fp16
// ---------------------------------------------------------------------------
__global__ __launch_bounds__(256) void wcvt_kernel(
    const float* __restrict__ W, __half* __restrict__ Wt, int K, int N)
{
    __shared__ float tile[32][33];
    int k0 = blockIdx.y * 32, n0 = blockIdx.x * 32;
    int tx = threadIdx.x & 31, ty = threadIdx.x >> 5;
#pragma unroll
    for (int j = 0; j < 4; j++)
        tile[ty + 8 * j][tx] = W[(size_t)(k0 + ty + 8 * j) * N + n0 + tx];
    __syncthreads();
#pragma unroll
    for (int j = 0; j < 4; j++) {
        int n = n0 + ty + 8 * j, k = k0 + tx;
        Wt[(size_t)n * K + k] = __float2half_rn(tile[tx][ty + 8 * j]);
    }
}

// ---------------------------------------------------------------------------
// FP16 flash attention with ldmatrix fragment loads (unchanged R11).
// ---------------------------------------------------------------------------
#define PST2 72
#define KST2 72
#define VST2 72
#define ATTN_SMEM ((128 * PST2 + 64 * KST2 + 64 * VST2) * 2)

__global__ __launch_bounds__(256) void attn_h(
    const __half* __restrict__ Qb, const __half* __restrict__ Kb,
    const __half* __restrict__ Vb, __half* __restrict__ Ob)
{
    extern __shared__ __half hsm[];
    __half* Ps = hsm;
    __half* Ks = Ps + 128 * PST2;
    __half* Vs = Ks + 64 * KST2;

    int bh = blockIdx.x;
    int b = bh >> 4, h = bh & 15;
    int q0 = blockIdx.y << 7;
    int t = threadIdx.x, w = t >> 5, lane = t & 31;
    int g = lane >> 2, tig = lane & 3;
    int qrow = w * 16 + g;

    size_t base = ((size_t)b * SEQ) * DMODEL + (size_t)h * DHEAD;
    const __half* Qp = Qb + base;
    const __half* Kp = Kb + base;
    const __half* Vp = Vb + base;

    uint32_t ps_b = (uint32_t)__cvta_generic_to_shared(Ps);
    uint32_t ks_b = (uint32_t)__cvta_generic_to_shared(Ks);
    uint32_t vs_b = (uint32_t)__cvta_generic_to_shared(Vs);

    int m4 = lane >> 3;
    uint32_t paddr = ps_b + (uint32_t)((w * 16 + (lane & 15)) * PST2 + (lane >> 4) * 8) * 2;
    uint32_t kaddr[4], vaddr[4];
#pragma unroll
    for (int p = 0; p < 4; p++) {
        int row = (2 * p + (m4 >> 1)) * 8 + (lane & 7);
        int col = (m4 & 1) * 8;
        kaddr[p] = ks_b + (uint32_t)(row * KST2 + col) * 2;
        vaddr[p] = vs_b + (uint32_t)(row * VST2 + col) * 2;
    }

    const __half2 sc = __floats2half2_rn(0.125f, 0.125f);
    for (int i = t; i < 128 * 8; i += 256) {
        int r = i >> 3, c8 = (i & 7) * 8;
        uint4 qv = *(const uint4*)&Qp[(size_t)(q0 + r) * DMODEL + c8];
        __half2* qh = (__half2*)&qv;
        qh[0] = __hmul2(qh[0], sc); qh[1] = __hmul2(qh[1], sc);
        qh[2] = __hmul2(qh[2], sc); qh[3] = __hmul2(qh[3], sc);
        *(uint4*)&Ps[r * PST2 + c8] = qv;
    }
    __syncthreads();

    uint32_t qf[4][4];
#pragma unroll
    for (int ks = 0; ks < 4; ks++)
        LDSM4(qf[ks][0], qf[ks][1], qf[ks][2], qf[ks][3], paddr + ks * 32);

    float oacc[8][4];
#pragma unroll
    for (int i = 0; i < 8; i++)
#pragma unroll
        for (int v = 0; v < 4; v++) oacc[i][v] = 0.f;
    float m_lo = -3.4e38f, m_hi = -3.4e38f, l_lo = 0.f, l_hi = 0.f;
    __syncthreads();

    for (int kt = 0; kt < SEQ / 64; kt++) {
        int k0 = kt << 6;
        for (int i = t; i < 64 * 8; i += 256) {
            int r = i >> 3, c8 = (i & 7) * 8;
            *(uint4*)&Ks[r * KST2 + c8] =
                *(const uint4*)&Kp[(size_t)(k0 + r) * DMODEL + c8];
        }
        for (int i = t; i < 64 * 16; i += 256) {
            int r = i >> 4, c4 = (i & 15) * 4;
            __half2 v01 = *(const __half2*)&Vp[(size_t)(k0 + r) * DMODEL + c4];
            __half2 v23 = *(const __half2*)&Vp[(size_t)(k0 + r) * DMODEL + c4 + 2];
            Vs[(c4 + 0) * VST2 + r] = __low2half(v01);
            Vs[(c4 + 1) * VST2 + r] = __high2half(v01);
            Vs[(c4 + 2) * VST2 + r] = __low2half(v23);
            Vs[(c4 + 3) * VST2 + r] = __high2half(v23);
        }
        __syncthreads();

        float sacc[8][4];
#pragma unroll
        for (int i = 0; i < 8; i++)
#pragma unroll
            for (int v = 0; v < 4; v++) sacc[i][v] = 0.f;
#pragma unroll
        for (int ks = 0; ks < 4; ks++) {
#pragma unroll
            for (int p = 0; p < 4; p++) {
                uint32_t b0, b1, b2, b3;
                LDSM4(b0, b1, b2, b3, kaddr[p] + ks * 32);
                MMA16816(sacc[2 * p],     qf[ks][0], qf[ks][1], qf[ks][2], qf[ks][3], b0, b1);
                MMA16816(sacc[2 * p + 1], qf[ks][0], qf[ks][1], qf[ks][2], qf[ks][3], b2, b3);
            }
        }

        float tl = -3.4e38f, th = -3.4e38f;
#pragma unroll
        for (int ni = 0; ni < 8; ni++) {
            tl = fmaxf(tl, fmaxf(sacc[ni][0], sacc[ni][1]));
            th = fmaxf(th, fmaxf(sacc[ni][2], sacc[ni][3]));
        }
        tl = fmaxf(tl, __shfl_xor_sync(0xffffffffu, tl, 1));
        tl = fmaxf(tl, __shfl_xor_sync(0xffffffffu, tl, 2));
        th = fmaxf(th, __shfl_xor_sync(0xffffffffu, th, 1));
        th = fmaxf(th, __shfl_xor_sync(0xffffffffu, th, 2));
        float nm_lo = fmaxf(m_lo, tl), nm_hi = fmaxf(m_hi, th);
        float corr_lo = __expf(m_lo - nm_lo), corr_hi = __expf(m_hi - nm_hi);
        m_lo = nm_lo; m_hi = nm_hi;

        float sum_lo = 0.f, sum_hi = 0.f;
#pragma unroll
        for (int ni = 0; ni < 8; ni++) {
            float e0 = __expf(sacc[ni][0] - nm_lo);
            float e1 = __expf(sacc[ni][1] - nm_lo);
            float e2 = __expf(sacc[ni][2] - nm_hi);
            float e3 = __expf(sacc[ni][3] - nm_hi);
            sum_lo += e0 + e1; sum_hi += e2 + e3;
            int c = ni * 8 + 2 * tig;
            *(__half2*)&Ps[qrow * PST2 + c]       = __floats2half2_rn(e0, e1);
            *(__half2*)&Ps[(qrow + 8) * PST2 + c] = __floats2half2_rn(e2, e3);
        }
        sum_lo += __shfl_xor_sync(0xffffffffu, sum_lo, 1);
        sum_lo += __shfl_xor_sync(0xffffffffu, sum_lo, 2);
        sum_hi += __shfl_xor_sync(0xffffffffu, sum_hi, 1);
        sum_hi += __shfl_xor_sync(0xffffffffu, sum_hi, 2);
        l_lo = l_lo * corr_lo + sum_lo;
        l_hi = l_hi * corr_hi + sum_hi;

#pragma unroll
        for (int ni = 0; ni < 8; ni++) {
            oacc[ni][0] *= corr_lo; oacc[ni][1] *= corr_lo;
            oacc[ni][2] *= corr_hi; oacc[ni][3] *= corr_hi;
        }
        __syncwarp();

#pragma unroll
        for (int ks = 0; ks < 4; ks++) {
            uint32_t pa0, pa1, pa2, pa3;
            LDSM4(pa0, pa1, pa2, pa3, paddr + ks * 32);
#pragma unroll
            for (int p = 0; p < 4; p++) {
                uint32_t b0, b1, b2, b3;
                LDSM4(b0, b1, b2, b3, vaddr[p] + ks * 32);
                MMA16816(oacc[2 * p],     pa0, pa1, pa2, pa3, b0, b1);
                MMA16816(oacc[2 * p + 1], pa0, pa1, pa2, pa3, b2, b3);
            }
        }
        __syncthreads();
    }

    float inv_lo = 1.f / l_lo, inv_hi = 1.f / l_hi;
    __half* Op = Ob + base;
#pragma unroll
    for (int ni = 0; ni < 8; ni++) {
        int c = ni * 8 + 2 * tig;
        *(__half2*)&Op[(size_t)(q0 + qrow) * DMODEL + c] =
            __floats2half2_rn(oacc[ni][0] * inv_lo, oacc[ni][1] * inv_lo);
        *(__half2*)&Op[(size_t)(q0 + qrow + 8) * DMODEL + c] =
            __floats2half2_rn(oacc[ni][2] * inv_hi, oacc[ni][3] * inv_hi);
    }
}

// ---------------------------------------------------------------------------
// FP16 GEMM, BK=64: 128x128x64 tiles, 2-stage, ldmatrix, m16n8k16.
// Stage stride 72 halfs (LDSM banks 4r mod 32, conflict-free).
// ---------------------------------------------------------------------------
#define HAST 72
#define HSTAGE_H (2 * 128 * HAST)              // 18432 halfs/stage
#define HGEMM_SMEM (2 * HSTAGE_H * 2)          // 73728 bytes

template <int EPI>
__global__ __launch_bounds__(256, 2) void hgemm(
    const __half* __restrict__ A, const __half* __restrict__ Bt,
    const float* __restrict__ bias, const float* __restrict__ resid,
    __half* __restrict__ C16, float* __restrict__ C32, int M, int N, int K)
{
    extern __shared__ __half hsm[];

    int tid = threadIdx.x;
    int wid = tid >> 5;
    int lane = tid & 31;
    int g = lane >> 2;
    int tig = lane & 3;
    int m0 = blockIdx.y * 128, n0 = blockIdx.x * 128;
    int m0w = (wid & 1) * 64;
    int n0w = (wid >> 1) * 32;
    int m4 = lane >> 3;

    float acc[4][4][4];
#pragma unroll
    for (int i = 0; i < 4; i++)
#pragma unroll
        for (int j = 0; j < 4; j++)
#pragma unroll
            for (int v = 0; v < 4; v++) acc[i][j][v] = 0.f;

    uint32_t smb = (uint32_t)__cvta_generic_to_shared(hsm);

    uint32_t aaddr[4], baddr[2];
#pragma unroll
    for (int mi = 0; mi < 4; mi++)
        aaddr[mi] = smb + (uint32_t)((m0w + mi * 16 + (lane & 15)) * HAST
                                     + (lane >> 4) * 8) * 2;
#pragma unroll
    for (int p = 0; p < 2; p++) {
        int row = n0w + (2 * p + (m4 >> 1)) * 8 + (lane & 7);
        int col = (m4 & 1) * 8;
        baddr[p] = smb + (uint32_t)(128 * HAST + row * HAST + col) * 2;
    }

    // BK=64 load: A tile 128x64 halfs = 1024 chunks(16B), B same -> 2048 total,
    // 8 chunks/thread. chunk c: tile=c>>10, cc=c&1023, row=cc>>3, q=cc&7.
#define HLOAD(K0, ST)                                                             \
    do {                                                                          \
        uint32_t sb = smb + (ST) * HSTAGE_H * 2;                                  \
        _Pragma("unroll")                                                         \
        for (int j = 0; j < 8; j++) {                                             \
            int c = tid + j * 256;                                                \
            int tile = c >> 10, cc = c & 1023, row = cc >> 3, q = cc & 7;         \
            const __half* gp = tile ? (Bt + (size_t)(n0 + row) * K + (K0) + q * 8)\
                                    : (A + (size_t)(m0 + row) * K + (K0) + q * 8);\
            uint32_t sp = sb + (uint32_t)(tile * 128 * HAST + row * HAST + q * 8) * 2; \
            asm volatile("cp.async.ca.shared.global [%0], [%1], 16;\n" ::         \
                "r"(sp), "l"(gp));                                                \
        }                                                                         \
    } while (0)

    int KT = K >> 6;   // K/64
    HLOAD(0, 0);
    asm volatile("cp.async.commit_group;\n");

    for (int kt = 0; kt < KT; kt++) {
        if (kt + 1 < KT) {
            HLOAD((kt + 1) << 6, (kt + 1) & 1);
            asm volatile("cp.async.commit_group;\n");
            asm volatile("cp.async.wait_group 1;\n");
        } else {
            asm volatile("cp.async.wait_group 0;\n");
        }
        __syncthreads();
        uint32_t stoff = (uint32_t)(kt & 1) * HSTAGE_H * 2;
#pragma unroll
        for (int ks = 0; ks < 4; ks++) {
            uint32_t ko = stoff + ks * 32;   // kk*2 bytes (kk = ks*16)
            uint32_t af[4][4], bf[4][2];
#pragma unroll
            for (int mi = 0; mi < 4; mi++)
                LDSM4(af[mi][0], af[mi][1], af[mi][2], af[mi][3], aaddr[mi] + ko);
#pragma unroll
            for (int p = 0; p < 2; p++)
                LDSM4(bf[2 * p][0], bf[2 * p][1], bf[2 * p + 1][0], bf[2 * p + 1][1],
                      baddr[p] + ko);
#pragma unroll
            for (int mi = 0; mi < 4; mi++)
#pragma unroll
                for (int ni = 0; ni < 4; ni++)
                    MMA16816(acc[mi][ni], af[mi][0], af[mi][1], af[mi][2], af[mi][3],
                             bf[ni][0], bf[ni][1]);
        }
        __syncthreads();
    }

#pragma unroll
    for (int mi = 0; mi < 4; mi++) {
        int r0 = m0 + m0w + mi * 16 + g;
#pragma unroll
        for (int ni = 0; ni < 4; ni++) {
            int c = n0 + n0w + ni * 8 + 2 * tig;
            float b0 = bias[c], b1 = bias[c + 1];
            float v0 = acc[mi][ni][0] + b0;
            float v1 = acc[mi][ni][1] + b1;
            float v2 = acc[mi][ni][2] + b0;
            float v3 = acc[mi][ni][3] + b1;
            if (EPI == 0) {
                v0 = fmaxf(v0, 0.f); v1 = fmaxf(v1, 0.f);
                v2 = fmaxf(v2, 0.f); v3 = fmaxf(v3, 0.f);
                *(__half2*)&C16[(size_t)r0 * N + c] = __floats2half2_rn(v0, v1);
                *(__half2*)&C16[(size_t)(r0 + 8) * N + c] = __floats2half2_rn(v2, v3);
            } else {
                v0 += resid[(size_t)r0 * N + c];
                v1 += resid[(size_t)r0 * N + c + 1];
                v2 += resid[(size_t)(r0 + 8) * N + c];
                v3 += resid[(size_t)(r0 + 8) * N + c + 1];
                *(float2*)&C32[(size_t)r0 * N + c] = make_float2(v0, v1);
                *(float2*)&C32[(size_t)(r0 + 8) * N + c] = make_float2(v2, v3);
            }
        }
    }
#undef HLOAD
}

// ---------------------------------------------------------------------------
extern "C" void kernel_launch(void* const* d_in, const int* in_sizes, int n_in,
                              void* d_out, int out_size)
{
    const float* tgt    = (const float*)d_in[0];
    const float* memory = (const float*)d_in[1];
    const float* sa_w   = (const float*)d_in[4];
    const float* sa_b   = (const float*)d_in[5];
    const float* mha_w  = (const float*)d_in[6];
    const float* mha_b  = (const float*)d_in[7];
    const float* ff_w1  = (const float*)d_in[8];
    const float* ff_b1  = (const float*)d_in[9];
    const float* ff_w2  = (const float*)d_in[10];
    const float* ff_b2  = (const float*)d_in[11];
    const float* ln1g   = (const float*)d_in[12];
    const float* ln1b   = (const float*)d_in[13];
    const float* ln2g   = (const float*)d_in[14];
    const float* ln2b   = (const float*)d_in[15];
    const float* ln3g   = (const float*)d_in[16];
    const float* ln3b   = (const float*)d_in[17];
    float* out = (float*)d_out;

    float *x1;
    __half *attn16, *h16, *mem16, *mid16, *wsat, *wmhat, *w1t, *w2t;
    cudaGetSymbolAddress((void**)&x1,     g_x1);
    cudaGetSymbolAddress((void**)&attn16, g_attn16);
    cudaGetSymbolAddress((void**)&h16,    g_h16);
    cudaGetSymbolAddress((void**)&mem16,  g_mem16);
    cudaGetSymbolAddress((void**)&mid16,  g_mid16);
    cudaGetSymbolAddress((void**)&wsat,   g_wsat);
    cudaGetSymbolAddress((void**)&wmhat,  g_wmhat);
    cudaGetSymbolAddress((void**)&w1t,    g_w1t);
    cudaGetSymbolAddress((void**)&w2t,    g_w2t);

    cudaFuncSetAttribute(attn_h, cudaFuncAttributeMaxDynamicSharedMemorySize, ATTN_SMEM);
    cudaFuncSetAttribute(hgemm<0>, cudaFuncAttributeMaxDynamicSharedMemorySize, HGEMM_SMEM);
    cudaFuncSetAttribute(hgemm<1>, cudaFuncAttributeMaxDynamicSharedMemorySize, HGEMM_SMEM);

    dim3 attn_grid(BATCH * NHEAD, SEQ / 128);
    dim3 gfc(DMODEL / 128, MROWS / 128);     // (8, 32)
    dim3 gff1(DFF / 128, MROWS / 128);       // (32, 32)

    // prep
    wcvt_kernel<<<dim3(DMODEL / 32, DMODEL / 32), 256>>>(sa_w, wsat, DMODEL, DMODEL);
    wcvt_kernel<<<dim3(DMODEL / 32, DMODEL / 32), 256>>>(mha_w, wmhat, DMODEL, DMODEL);
    wcvt_kernel<<<dim3(DFF / 32, DMODEL / 32), 256>>>(ff_w1, w1t, DMODEL, DFF);
    wcvt_kernel<<<dim3(DMODEL / 32, DFF / 32), 256>>>(ff_w2, w2t, DFF, DMODEL);
    cvt16_kernel<<<MROWS * DMODEL / 4 / 256, 256>>>(memory, mem16, MROWS * DMODEL / 4);

    // ---- self-attention block ----
    ln_kernel<<<MROWS, 256>>>(tgt, ln1g, ln1b, h16);
    attn_h<<<attn_grid, 256, ATTN_SMEM>>>(h16, h16, h16, attn16);
    hgemm<1><<<gfc, 256, HGEMM_SMEM>>>(attn16, wsat, sa_b, tgt,
                                       nullptr, x1, MROWS, DMODEL, DMODEL);
    // ---- cross-attention block (Q=K=memory, V=LN2(x)) ----
    ln_kernel<<<MROWS, 256>>>(x1, ln2g, ln2b, h16);
    attn_h<<<attn_grid, 256, ATTN_SMEM>>>(mem16, mem16, h16, attn16);
    hgemm<1><<<gfc, 256, HGEMM_SMEM>>>(attn16, wmhat, mha_b, x1,
                                       nullptr, out, MROWS, DMODEL, DMODEL);
    // ---- FFN block ----
    ln_kernel<<<MROWS, 256>>>(out, ln3g, ln3b, h16);
    hgemm<0><<<gff1, 256, HGEMM_SMEM>>>(h16, w1t, ff_b1, nullptr,
                                        mid16, nullptr, MROWS, DFF, DMODEL);
    hgemm<1><<<gfc, 256, HGEMM_SMEM>>>(mid16, w2t, ff_b2, out,
                                       nullptr, out, MROWS, DMODEL, DFF);
}

// round 13
// speedup vs baseline: 2.4085x; 1.1888x over previous
#include <cuda_runtime.h>
#include <cuda_fp16.h>
#include <math.h>
#include <stdint.h>

#define BATCH 4
#define SEQ 1024
#define DMODEL 1024
#define NHEAD 16
#define DHEAD 64
#define DFF 4096
#define MROWS (BATCH * SEQ)

__device__ float g_x1[MROWS * DMODEL];
__device__ __half g_attn16[MROWS * DMODEL];
__device__ __half g_h16[MROWS * DMODEL];
__device__ __half g_mem16[MROWS * DMODEL];
__device__ __half g_mid16[MROWS * DFF];
__device__ __half g_wsat[DMODEL * DMODEL];
__device__ __half g_wmhat[DMODEL * DMODEL];
__device__ __half g_w1t[DFF * DMODEL];
__device__ __half g_w2t[DMODEL * DFF];

#define LDSM4(r0, r1, r2, r3, addr)                                        \
    asm volatile("ldmatrix.sync.aligned.m8n8.x4.shared.b16 "               \
                 "{%0,%1,%2,%3}, [%4];"                                    \
                 : "=r"(r0), "=r"(r1), "=r"(r2), "=r"(r3) : "r"(addr))

#define LDSM4T(r0, r1, r2, r3, addr)                                       \
    asm volatile("ldmatrix.sync.aligned.m8n8.x4.trans.shared.b16 "         \
                 "{%0,%1,%2,%3}, [%4];"                                    \
                 : "=r"(r0), "=r"(r1), "=r"(r2), "=r"(r3) : "r"(addr))

#define MMA16816(d, a0, a1, a2, a3, b0, b1)                                \
    asm volatile("mma.sync.aligned.m16n8k16.row.col.f32.f16.f16.f32 "      \
                 "{%0,%1,%2,%3}, {%4,%5,%6,%7}, {%8,%9}, {%0,%1,%2,%3};\n" \
                 : "+f"(d[0]), "+f"(d[1]), "+f"(d[2]), "+f"(d[3])          \
                 : "r"(a0), "r"(a1), "r"(a2), "r"(a3), "r"(b0), "r"(b1))

// ---------------------------------------------------------------------------
__global__ __launch_bounds__(256) void cvt16_kernel(
    const float* __restrict__ in, __half* __restrict__ out, int n4)
{
    int i = blockIdx.x * 256 + threadIdx.x;
    if (i < n4) {
        float4 v = ((const float4*)in)[i];
        ((__half2*)out)[2 * i]     = __floats2half2_rn(v.x, v.y);
        ((__half2*)out)[2 * i + 1] = __floats2half2_rn(v.z, v.w);
    }
}

// ---------------------------------------------------------------------------
__global__ __launch_bounds__(256) void ln_kernel(
    const float* __restrict__ x, const float* __restrict__ gam,
    const float* __restrict__ bet, __half* __restrict__ out16)
{
    int row = blockIdx.x;
    const float* xr = x + (size_t)row * DMODEL;
    float v[4];
    float s = 0.f, s2 = 0.f;
#pragma unroll
    for (int i = 0; i < 4; i++) {
        v[i] = xr[threadIdx.x + i * 256];
        s += v[i];
        s2 += v[i] * v[i];
    }
#pragma unroll
    for (int o = 16; o; o >>= 1) {
        s  += __shfl_xor_sync(0xffffffffu, s, o);
        s2 += __shfl_xor_sync(0xffffffffu, s2, o);
    }
    __shared__ float red[2][8];
    int w = threadIdx.x >> 5, l = threadIdx.x & 31;
    if (l == 0) { red[0][w] = s; red[1][w] = s2; }
    __syncthreads();
    s = 0.f; s2 = 0.f;
#pragma unroll
    for (int i = 0; i < 8; i++) { s += red[0][i]; s2 += red[1][i]; }
    float mean = s * (1.0f / DMODEL);
    float var  = s2 * (1.0f / DMODEL) - mean * mean;
    float rstd = rsqrtf(var + 1e-5f);
#pragma unroll
    for (int i = 0; i < 4; i++) {
        int c = threadIdx.x + i * 256;
        float y = (v[i] - mean) * rstd * gam[c] + bet[c];
        out16[(size_t)row * DMODEL + c] = __float2half_rn(y);
    }
}

// ---------------------------------------------------------------------------
__global__ __launch_bounds__(256) void wcvt_kernel(
    const float* __restrict__ W, __half* __restrict__ Wt, int K, int N)
{
    __shared__ float tile[32][33];
    int k0 = blockIdx.y * 32, n0 = blockIdx.x * 32;
    int tx = threadIdx.x & 31, ty = threadIdx.x >> 5;
#pragma unroll
    for (int j = 0; j < 4; j++)
        tile[ty + 8 * j][tx] = W[(size_t)(k0 + ty + 8 * j) * N + n0 + tx];
    __syncthreads();
#pragma unroll
    for (int j = 0; j < 4; j++) {
        int n = n0 + ty + 8 * j, k = k0 + tx;
        Wt[(size_t)n * K + k] = __float2half_rn(tile[tx][ty + 8 * j]);
    }
}

// ---------------------------------------------------------------------------
// FP16 flash attention: cp.async 2-stage K/V pipeline, ldmatrix(+trans) frags.
// Ps[128][72] (Q then P); per stage Ks[64][72] row=key, Vs[64][72] row=key.
// ---------------------------------------------------------------------------
#define PST2 72
#define KVST 72
#define KVSTAGE_H (2 * 64 * KVST)              // K + V per stage (halfs)
#define ATTN_SMEM ((128 * PST2 + 2 * KVSTAGE_H) * 2)

__global__ __launch_bounds__(256, 2) void attn_h(
    const __half* __restrict__ Qb, const __half* __restrict__ Kb,
    const __half* __restrict__ Vb, __half* __restrict__ Ob)
{
    extern __shared__ __half hsm[];
    __half* Ps = hsm;

    int bh = blockIdx.x;
    int b = bh >> 4, h = bh & 15;
    int q0 = blockIdx.y << 7;
    int t = threadIdx.x, w = t >> 5, lane = t & 31;
    int g = lane >> 2, tig = lane & 3;
    int qrow = w * 16 + g;

    size_t base = ((size_t)b * SEQ) * DMODEL + (size_t)h * DHEAD;
    const __half* Qp = Qb + base;
    const __half* Kp = Kb + base;
    const __half* Vp = Vb + base;

    uint32_t ps_b = (uint32_t)__cvta_generic_to_shared(Ps);
    uint32_t kv_b = ps_b + 128 * PST2 * 2;     // stage 0 K base (bytes)

    int m4 = lane >> 3;
    uint32_t paddr = ps_b + (uint32_t)((w * 16 + (lane & 15)) * PST2 + (lane >> 4) * 8) * 2;
    // K frag (non-trans): row over key, col over d
    uint32_t koff[4], voff[4];
#pragma unroll
    for (int p = 0; p < 4; p++) {
        int krow = (2 * p + (m4 >> 1)) * 8 + (lane & 7);
        int kcol = (m4 & 1) * 8;
        koff[p] = (uint32_t)(krow * KVST + kcol) * 2;
        // V frag (trans): row over key (=k), col over d (=n)
        int vrow = (m4 & 1) * 8 + (lane & 7);
        int vcol = (2 * p + (m4 >> 1)) * 8;
        voff[p] = (uint32_t)(64 * KVST + vrow * KVST + vcol) * 2;
    }

    // Stage Q (scaled 1/8)
    const __half2 sc = __floats2half2_rn(0.125f, 0.125f);
    for (int i = t; i < 128 * 8; i += 256) {
        int r = i >> 3, c8 = (i & 7) * 8;
        uint4 qv = *(const uint4*)&Qp[(size_t)(q0 + r) * DMODEL + c8];
        __half2* qh = (__half2*)&qv;
        qh[0] = __hmul2(qh[0], sc); qh[1] = __hmul2(qh[1], sc);
        qh[2] = __hmul2(qh[2], sc); qh[3] = __hmul2(qh[3], sc);
        *(uint4*)&Ps[r * PST2 + c8] = qv;
    }

    // K/V stage load: 64 rows x 8 chunks each, 2 chunks/thread/array
#define LOADKV(KT_, ST_)                                                          \
    do {                                                                          \
        uint32_t sb = kv_b + (ST_) * KVSTAGE_H * 2;                               \
        int k0_ = (KT_) << 6;                                                     \
        _Pragma("unroll")                                                         \
        for (int j = 0; j < 2; j++) {                                             \
            int c = t + j * 256;                                                  \
            int r = c >> 3, q = c & 7;                                            \
            asm volatile("cp.async.ca.shared.global [%0], [%1], 16;\n" ::         \
                "r"(sb + (uint32_t)(r * KVST + q * 8) * 2),                       \
                "l"(Kp + (size_t)(k0_ + r) * DMODEL + q * 8));                    \
            asm volatile("cp.async.ca.shared.global [%0], [%1], 16;\n" ::         \
                "r"(sb + (uint32_t)(64 * KVST + r * KVST + q * 8) * 2),           \
                "l"(Vp + (size_t)(k0_ + r) * DMODEL + q * 8));                    \
        }                                                                         \
        asm volatile("cp.async.commit_group;\n");                                 \
    } while (0)

    LOADKV(0, 0);
    __syncthreads();   // Q staged

    uint32_t qf[4][4];
#pragma unroll
    for (int ks = 0; ks < 4; ks++)
        LDSM4(qf[ks][0], qf[ks][1], qf[ks][2], qf[ks][3], paddr + ks * 32);

    float oacc[8][4];
#pragma unroll
    for (int i = 0; i < 8; i++)
#pragma unroll
        for (int v = 0; v < 4; v++) oacc[i][v] = 0.f;
    float m_lo = -3.4e38f, m_hi = -3.4e38f, l_lo = 0.f, l_hi = 0.f;
    __syncthreads();   // qf built before Ps reused for P

    const int KT = SEQ / 64;
    for (int kt = 0; kt < KT; kt++) {
        int st = kt & 1;
        if (kt + 1 < KT) {
            LOADKV(kt + 1, st ^ 1);
            asm volatile("cp.async.wait_group 1;\n");
        } else {
            asm volatile("cp.async.wait_group 0;\n");
        }
        __syncthreads();
        uint32_t sbase = kv_b + (uint32_t)st * KVSTAGE_H * 2;

        // ---- S = Q @ K^T ----
        float sacc[8][4];
#pragma unroll
        for (int i = 0; i < 8; i++)
#pragma unroll
            for (int v = 0; v < 4; v++) sacc[i][v] = 0.f;
#pragma unroll
        for (int ks = 0; ks < 4; ks++) {
#pragma unroll
            for (int p = 0; p < 4; p++) {
                uint32_t b0, b1, b2, b3;
                LDSM4(b0, b1, b2, b3, sbase + koff[p] + ks * 32);
                MMA16816(sacc[2 * p],     qf[ks][0], qf[ks][1], qf[ks][2], qf[ks][3], b0, b1);
                MMA16816(sacc[2 * p + 1], qf[ks][0], qf[ks][1], qf[ks][2], qf[ks][3], b2, b3);
            }
        }

        // ---- online softmax ----
        float tl = -3.4e38f, th = -3.4e38f;
#pragma unroll
        for (int ni = 0; ni < 8; ni++) {
            tl = fmaxf(tl, fmaxf(sacc[ni][0], sacc[ni][1]));
            th = fmaxf(th, fmaxf(sacc[ni][2], sacc[ni][3]));
        }
        tl = fmaxf(tl, __shfl_xor_sync(0xffffffffu, tl, 1));
        tl = fmaxf(tl, __shfl_xor_sync(0xffffffffu, tl, 2));
        th = fmaxf(th, __shfl_xor_sync(0xffffffffu, th, 1));
        th = fmaxf(th, __shfl_xor_sync(0xffffffffu, th, 2));
        float nm_lo = fmaxf(m_lo, tl), nm_hi = fmaxf(m_hi, th);
        float corr_lo = __expf(m_lo - nm_lo), corr_hi = __expf(m_hi - nm_hi);
        m_lo = nm_lo; m_hi = nm_hi;

        float sum_lo = 0.f, sum_hi = 0.f;
#pragma unroll
        for (int ni = 0; ni < 8; ni++) {
            float e0 = __expf(sacc[ni][0] - nm_lo);
            float e1 = __expf(sacc[ni][1] - nm_lo);
            float e2 = __expf(sacc[ni][2] - nm_hi);
            float e3 = __expf(sacc[ni][3] - nm_hi);
            sum_lo += e0 + e1; sum_hi += e2 + e3;
            int c = ni * 8 + 2 * tig;
            *(__half2*)&Ps[qrow * PST2 + c]       = __floats2half2_rn(e0, e1);
            *(__half2*)&Ps[(qrow + 8) * PST2 + c] = __floats2half2_rn(e2, e3);
        }
        sum_lo += __shfl_xor_sync(0xffffffffu, sum_lo, 1);
        sum_lo += __shfl_xor_sync(0xffffffffu, sum_lo, 2);
        sum_hi += __shfl_xor_sync(0xffffffffu, sum_hi, 1);
        sum_hi += __shfl_xor_sync(0xffffffffu, sum_hi, 2);
        l_lo = l_lo * corr_lo + sum_lo;
        l_hi = l_hi * corr_hi + sum_hi;

#pragma unroll
        for (int ni = 0; ni < 8; ni++) {
            oacc[ni][0] *= corr_lo; oacc[ni][1] *= corr_lo;
            oacc[ni][2] *= corr_hi; oacc[ni][3] *= corr_hi;
        }
        __syncwarp();

        // ---- O += P @ V (V row-major, ldmatrix.trans) ----
#pragma unroll
        for (int ks = 0; ks < 4; ks++) {
            uint32_t pa0, pa1, pa2, pa3;
            LDSM4(pa0, pa1, pa2, pa3, paddr + ks * 32);
            uint32_t krow_off = (uint32_t)(ks * 16 * KVST) * 2;
#pragma unroll
            for (int p = 0; p < 4; p++) {
                uint32_t b0, b1, b2, b3;
                LDSM4T(b0, b1, b2, b3, sbase + voff[p] + krow_off);
                MMA16816(oacc[2 * p],     pa0, pa1, pa2, pa3, b0, b1);
                MMA16816(oacc[2 * p + 1], pa0, pa1, pa2, pa3, b2, b3);
            }
        }
        __syncthreads();
    }

    float inv_lo = 1.f / l_lo, inv_hi = 1.f / l_hi;
    __half* Op = Ob + base;
#pragma unroll
    for (int ni = 0; ni < 8; ni++) {
        int c = ni * 8 + 2 * tig;
        *(__half2*)&Op[(size_t)(q0 + qrow) * DMODEL + c] =
            __floats2half2_rn(oacc[ni][0] * inv_lo, oacc[ni][1] * inv_lo);
        *(__half2*)&Op[(size_t)(q0 + qrow + 8) * DMODEL + c] =
            __floats2half2_rn(oacc[ni][2] * inv_hi, oacc[ni][3] * inv_hi);
    }
#undef LOADKV
}

// ---------------------------------------------------------------------------
// FP16 GEMM, BK=64 (unchanged R12)
// ---------------------------------------------------------------------------
#define HAST 72
#define HSTAGE_H (2 * 128 * HAST)
#define HGEMM_SMEM (2 * HSTAGE_H * 2)

template <int EPI>
__global__ __launch_bounds__(256, 2) void hgemm(
    const __half* __restrict__ A, const __half* __restrict__ Bt,
    const float* __restrict__ bias, const float* __restrict__ resid,
    __half* __restrict__ C16, float* __restrict__ C32, int M, int N, int K)
{
    extern __shared__ __half hsm[];

    int tid = threadIdx.x;
    int wid = tid >> 5;
    int lane = tid & 31;
    int g = lane >> 2;
    int tig = lane & 3;
    int m0 = blockIdx.y * 128, n0 = blockIdx.x * 128;
    int m0w = (wid & 1) * 64;
    int n0w = (wid >> 1) * 32;
    int m4 = lane >> 3;

    float acc[4][4][4];
#pragma unroll
    for (int i = 0; i < 4; i++)
#pragma unroll
        for (int j = 0; j < 4; j++)
#pragma unroll
            for (int v = 0; v < 4; v++) acc[i][j][v] = 0.f;

    uint32_t smb = (uint32_t)__cvta_generic_to_shared(hsm);

    uint32_t aaddr[4], baddr[2];
#pragma unroll
    for (int mi = 0; mi < 4; mi++)
        aaddr[mi] = smb + (uint32_t)((m0w + mi * 16 + (lane & 15)) * HAST
                                     + (lane >> 4) * 8) * 2;
#pragma unroll
    for (int p = 0; p < 2; p++) {
        int row = n0w + (2 * p + (m4 >> 1)) * 8 + (lane & 7);
        int col = (m4 & 1) * 8;
        baddr[p] = smb + (uint32_t)(128 * HAST + row * HAST + col) * 2;
    }

#define HLOAD(K0, ST)                                                             \
    do {                                                                          \
        uint32_t sb = smb + (ST) * HSTAGE_H * 2;                                  \
        _Pragma("unroll")                                                         \
        for (int j = 0; j < 8; j++) {                                             \
            int c = tid + j * 256;                                                \
            int tile = c >> 10, cc = c & 1023, row = cc >> 3, q = cc & 7;         \
            const __half* gp = tile ? (Bt + (size_t)(n0 + row) * K + (K0) + q * 8)\
                                    : (A + (size_t)(m0 + row) * K + (K0) + q * 8);\
            uint32_t sp = sb + (uint32_t)(tile * 128 * HAST + row * HAST + q * 8) * 2; \
            asm volatile("cp.async.ca.shared.global [%0], [%1], 16;\n" ::         \
                "r"(sp), "l"(gp));                                                \
        }                                                                         \
    } while (0)

    int KT = K >> 6;
    HLOAD(0, 0);
    asm volatile("cp.async.commit_group;\n");

    for (int kt = 0; kt < KT; kt++) {
        if (kt + 1 < KT) {
            HLOAD((kt + 1) << 6, (kt + 1) & 1);
            asm volatile("cp.async.commit_group;\n");
            asm volatile("cp.async.wait_group 1;\n");
        } else {
            asm volatile("cp.async.wait_group 0;\n");
        }
        __syncthreads();
        uint32_t stoff = (uint32_t)(kt & 1) * HSTAGE_H * 2;
#pragma unroll
        for (int ks = 0; ks < 4; ks++) {
            uint32_t ko = stoff + ks * 32;
            uint32_t af[4][4], bf[4][2];
#pragma unroll
            for (int mi = 0; mi < 4; mi++)
                LDSM4(af[mi][0], af[mi][1], af[mi][2], af[mi][3], aaddr[mi] + ko);
#pragma unroll
            for (int p = 0; p < 2; p++)
                LDSM4(bf[2 * p][0], bf[2 * p][1], bf[2 * p + 1][0], bf[2 * p + 1][1],
                      baddr[p] + ko);
#pragma unroll
            for (int mi = 0; mi < 4; mi++)
#pragma unroll
                for (int ni = 0; ni < 4; ni++)
                    MMA16816(acc[mi][ni], af[mi][0], af[mi][1], af[mi][2], af[mi][3],
                             bf[ni][0], bf[ni][1]);
        }
        __syncthreads();
    }

#pragma unroll
    for (int mi = 0; mi < 4; mi++) {
        int r0 = m0 + m0w + mi * 16 + g;
#pragma unroll
        for (int ni = 0; ni < 4; ni++) {
            int c = n0 + n0w + ni * 8 + 2 * tig;
            float b0 = bias[c], b1 = bias[c + 1];
            float v0 = acc[mi][ni][0] + b0;
            float v1 = acc[mi][ni][1] + b1;
            float v2 = acc[mi][ni][2] + b0;
            float v3 = acc[mi][ni][3] + b1;
            if (EPI == 0) {
                v0 = fmaxf(v0, 0.f); v1 = fmaxf(v1, 0.f);
                v2 = fmaxf(v2, 0.f); v3 = fmaxf(v3, 0.f);
                *(__half2*)&C16[(size_t)r0 * N + c] = __floats2half2_rn(v0, v1);
                *(__half2*)&C16[(size_t)(r0 + 8) * N + c] = __floats2half2_rn(v2, v3);
            } else {
                v0 += resid[(size_t)r0 * N + c];
                v1 += resid[(size_t)r0 * N + c + 1];
                v2 += resid[(size_t)(r0 + 8) * N + c];
                v3 += resid[(size_t)(r0 + 8) * N + c + 1];
                *(float2*)&C32[(size_t)r0 * N + c] = make_float2(v0, v1);
                *(float2*)&C32[(size_t)(r0 + 8) * N + c] = make_float2(v2, v3);
            }
        }
    }
#undef HLOAD
}

// ---------------------------------------------------------------------------
extern "C" void kernel_launch(void* const* d_in, const int* in_sizes, int n_in,
                              void* d_out, int out_size)
{
    const float* tgt    = (const float*)d_in[0];
    const float* memory = (const float*)d_in[1];
    const float* sa_w   = (const float*)d_in[4];
    const float* sa_b   = (const float*)d_in[5];
    const float* mha_w  = (const float*)d_in[6];
    const float* mha_b  = (const float*)d_in[7];
    const float* ff_w1  = (const float*)d_in[8];
    const float* ff_b1  = (const float*)d_in[9];
    const float* ff_w2  = (const float*)d_in[10];
    const float* ff_b2  = (const float*)d_in[11];
    const float* ln1g   = (const float*)d_in[12];
    const float* ln1b   = (const float*)d_in[13];
    const float* ln2g   = (const float*)d_in[14];
    const float* ln2b   = (const float*)d_in[15];
    const float* ln3g   = (const float*)d_in[16];
    const float* ln3b   = (const float*)d_in[17];
    float* out = (float*)d_out;

    float *x1;
    __half *attn16, *h16, *mem16, *mid16, *wsat, *wmhat, *w1t, *w2t;
    cudaGetSymbolAddress((void**)&x1,     g_x1);
    cudaGetSymbolAddress((void**)&attn16, g_attn16);
    cudaGetSymbolAddress((void**)&h16,    g_h16);
    cudaGetSymbolAddress((void**)&mem16,  g_mem16);
    cudaGetSymbolAddress((void**)&mid16,  g_mid16);
    cudaGetSymbolAddress((void**)&wsat,   g_wsat);
    cudaGetSymbolAddress((void**)&wmhat,  g_wmhat);
    cudaGetSymbolAddress((void**)&w1t,    g_w1t);
    cudaGetSymbolAddress((void**)&w2t,    g_w2t);

    cudaFuncSetAttribute(attn_h, cudaFuncAttributeMaxDynamicSharedMemorySize, ATTN_SMEM);
    cudaFuncSetAttribute(hgemm<0>, cudaFuncAttributeMaxDynamicSharedMemorySize, HGEMM_SMEM);
    cudaFuncSetAttribute(hgemm<1>, cudaFuncAttributeMaxDynamicSharedMemorySize, HGEMM_SMEM);

    dim3 attn_grid(BATCH * NHEAD, SEQ / 128);
    dim3 gfc(DMODEL / 128, MROWS / 128);
    dim3 gff1(DFF / 128, MROWS / 128);

    wcvt_kernel<<<dim3(DMODEL / 32, DMODEL / 32), 256>>>(sa_w, wsat, DMODEL, DMODEL);
    wcvt_kernel<<<dim3(DMODEL / 32, DMODEL / 32), 256>>>(mha_w, wmhat, DMODEL, DMODEL);
    wcvt_kernel<<<dim3(DFF / 32, DMODEL / 32), 256>>>(ff_w1, w1t, DMODEL, DFF);
    wcvt_kernel<<<dim3(DMODEL / 32, DFF / 32), 256>>>(ff_w2, w2t, DFF, DMODEL);
    cvt16_kernel<<<MROWS * DMODEL / 4 / 256, 256>>>(memory, mem16, MROWS * DMODEL / 4);

    ln_kernel<<<MROWS, 256>>>(tgt, ln1g, ln1b, h16);
    attn_h<<<attn_grid, 256, ATTN_SMEM>>>(h16, h16, h16, attn16);
    hgemm<1><<<gfc, 256, HGEMM_SMEM>>>(attn16, wsat, sa_b, tgt,
                                       nullptr, x1, MROWS, DMODEL, DMODEL);
    ln_kernel<<<MROWS, 256>>>(x1, ln2g, ln2b, h16);
    attn_h<<<attn_grid, 256, ATTN_SMEM>>>(mem16, mem16, h16, attn16);
    hgemm<1><<<gfc, 256, HGEMM_SMEM>>>(attn16, wmhat, mha_b, x1,
                                       nullptr, out, MROWS, DMODEL, DMODEL);
    ln_kernel<<<MROWS, 256>>>(out, ln3g, ln3b, h16);
    hgemm<0><<<gff1, 256, HGEMM_SMEM>>>(h16, w1t, ff_b1, nullptr,
                                        mid16, nullptr, MROWS, DFF, DMODEL);
    hgemm<1><<<gfc, 256, HGEMM_SMEM>>>(mid16, w2t, ff_b2, out,
                                       nullptr, out, MROWS, DMODEL, DFF);
}